// round 8
// baseline (speedup 1.0000x reference)
#include <cuda_runtime.h>
#include <cstdint>

#define N_NODES 50000
#define N_EDGES 800000
#define FDIM    128
#define HDIM    128
#define TDIM    10

// Scratch (device globals) — only ever referenced from DEVICE code.
__device__ __align__(16) float g_dinv[N_NODES];
__device__ __align__(16) float g_norm[N_EDGES];
__device__ int  g_cnt[N_NODES];
__device__ int  g_rowptr[N_NODES];
__device__ int  g_cursor[N_NODES];
__device__ __align__(16) int2  g_edges[N_EDGES];   // (src, norm bits), grouped by dst
__device__ __align__(16) float g_T1[N_NODES * FDIM];
__device__ __align__(16) float g_T2[N_NODES * FDIM];

// ---------------------------------------------------------------------------
// Stage 0: zero degree / per-dst count
// ---------------------------------------------------------------------------
__global__ void init_kernel() {
    int n = blockIdx.x * blockDim.x + threadIdx.x;
    if (n < N_NODES) { g_dinv[n] = 0.f; g_cnt[n] = 0; }
}

// Stage 1: deg[src] += w ; cnt[dst] += 1        (edge_index is int32)
__global__ void deg_kernel(const int* __restrict__ ei,
                           const float* __restrict__ ew) {
    int e = blockIdx.x * blockDim.x + threadIdx.x;
    if (e < N_EDGES) {
        atomicAdd(&g_dinv[ei[e]], ew[e]);
        atomicAdd(&g_cnt[ei[N_EDGES + e]], 1);
    }
}

// Stage 2: dinv = deg > 0 ? rsqrt(deg) : 0
__global__ void dinv_kernel() {
    int n = blockIdx.x * blockDim.x + threadIdx.x;
    if (n < N_NODES) {
        float d = g_dinv[n];
        g_dinv[n] = (d > 0.f) ? rsqrtf(d) : 0.f;
    }
}

// Stage 3: norm[e] = -dinv[src] * w[e] * dinv[dst]
__global__ void norm_kernel(const int* __restrict__ ei,
                            const float* __restrict__ ew) {
    int e = blockIdx.x * blockDim.x + threadIdx.x;
    if (e < N_EDGES) {
        int s = ei[e];
        int d = ei[N_EDGES + e];
        g_norm[e] = -g_dinv[s] * ew[e] * g_dinv[d];
    }
}

// ---------------------------------------------------------------------------
// Stage 4: brute-force exclusive scan of g_cnt -> g_rowptr (+ cursor copy)
// ---------------------------------------------------------------------------
#define SCAN_THREADS 1024
#define SCAN_CHUNK   ((N_NODES + SCAN_THREADS - 1) / SCAN_THREADS)   // 49

__global__ void scan_kernel() {
    __shared__ int psum[SCAN_THREADS];
    const int tid = threadIdx.x;
    const int lo  = tid * SCAN_CHUNK;
    const int hi  = min(lo + SCAN_CHUNK, N_NODES);

    int s = 0;
    for (int i = lo; i < hi; i++) s += g_cnt[i];
    psum[tid] = s;
    __syncthreads();

    if (tid == 0) {
        int running = 0;
        for (int i = 0; i < SCAN_THREADS; i++) {
            int t = psum[i];
            psum[i] = running;
            running += t;
        }
    }
    __syncthreads();

    int base = psum[tid];
    for (int i = lo; i < hi; i++) {
        g_rowptr[i] = base;
        g_cursor[i] = base;
        base += g_cnt[i];
    }
}

// Stage 5: scatter packed (src, norm) into dst-grouped CSR slots
__global__ void scatter_kernel(const int* __restrict__ ei) {
    int e = blockIdx.x * blockDim.x + threadIdx.x;
    if (e < N_EDGES) {
        int s = ei[e];
        int d = ei[N_EDGES + e];
        int pos = atomicAdd(&g_cursor[d], 1);
        g_edges[pos] = make_int2(s, __float_as_int(g_norm[e]));
    }
}

// ---------------------------------------------------------------------------
// Stage 6/7: gather-side propagation, one warp per dst node.
// ---------------------------------------------------------------------------
__global__ void prop1_csr_kernel(const float* __restrict__ x) {
    int node = (blockIdx.x * blockDim.x + threadIdx.x) >> 5;
    int lane = threadIdx.x & 31;
    if (node >= N_NODES) return;
    int base = g_rowptr[node];
    int cnt  = g_cnt[node];

    float4 acc = make_float4(0.f, 0.f, 0.f, 0.f);
    for (int j = 0; j < cnt; j++) {
        int2 e0 = g_edges[base + j];
        float w0 = __int_as_float(e0.y);
        float4 v0 = ((const float4*)(x + (size_t)e0.x * FDIM))[lane];
        acc.x += w0 * v0.x; acc.y += w0 * v0.y;
        acc.z += w0 * v0.z; acc.w += w0 * v0.w;
    }
    ((float4*)(g_T1 + (size_t)node * FDIM))[lane] = acc;
}

__global__ void prop2_csr_kernel(const float* __restrict__ x) {
    int node = (blockIdx.x * blockDim.x + threadIdx.x) >> 5;
    int lane = threadIdx.x & 31;
    if (node >= N_NODES) return;
    int base = g_rowptr[node];
    int cnt  = g_cnt[node];

    float4 acc = make_float4(0.f, 0.f, 0.f, 0.f);
    for (int j = 0; j < cnt; j++) {
        int2 e0 = g_edges[base + j];
        float w0 = __int_as_float(e0.y);
        float4 v0 = ((const float4*)(g_T1 + (size_t)e0.x * FDIM))[lane];
        acc.x += w0 * v0.x; acc.y += w0 * v0.y;
        acc.z += w0 * v0.z; acc.w += w0 * v0.w;
    }
    float4 xx = ((const float4*)(x + (size_t)node * FDIM))[lane];
    acc.x = 2.f * acc.x - xx.x;
    acc.y = 2.f * acc.y - xx.y;
    acc.z = 2.f * acc.z - xx.z;
    acc.w = 2.f * acc.w - xx.w;
    ((float4*)(g_T2 + (size_t)node * FDIM))[lane] = acc;
}

// ---------------------------------------------------------------------------
// Stage 8: fused GEMM + gate epilogue + output projection
// Inner loop uses Blackwell packed fma.rn.f32x2 (exact fp32, 2 FMA/issue).
// ---------------------------------------------------------------------------
#define BM  64
#define BK  32
#define NKB 12
#define STAGE_FLOATS (BM*BK + BK*256)   // 10240

extern __shared__ float smem[];

__device__ __forceinline__ void cp_async16(uint32_t saddr, const float* g, int bytes) {
    asm volatile("cp.async.cg.shared.global [%0], [%1], 16, %2;"
                 :: "r"(saddr), "l"(g), "r"(bytes) : "memory");
}

#define FMA2(d, a, b, c) \
    asm("fma.rn.f32x2 %0, %1, %2, %3;" : "=l"(d) : "l"(a), "l"(b), "l"(c))

__global__ __launch_bounds__(256, 2) void fused_kernel(
    const float* __restrict__ x,
    const float* __restrict__ Wz, const float* __restrict__ Wh,
    const float* __restrict__ bz0, const float* __restrict__ bz1,
    const float* __restrict__ bh0, const float* __restrict__ bh1,
    const float* __restrict__ Wlin, const float* __restrict__ blin,
    float* __restrict__ out)
{
    const int tid = threadIdx.x;
    const int tx  = tid & 15;
    const int ty  = tid >> 4;
    const int m0  = blockIdx.x * BM;

    const uint32_t smem_u32 = (uint32_t)__cvta_generic_to_shared(smem);

    // packed accumulators: czp[r][i] holds columns (2i, 2i+1) of matrix Z
    unsigned long long czp[4][4];
    unsigned long long chp[4][4];
#pragma unroll
    for (int r = 0; r < 4; r++)
#pragma unroll
        for (int i = 0; i < 4; i++) { czp[r][i] = 0ULL; chp[r][i] = 0ULL; }

    auto load_stage = [&](int kb, int s) {
        const int col = kb * BK;
        const float* Asrc;
        int c0;
        if (col < 128)      { Asrc = x;    c0 = col; }
        else if (col < 256) { Asrc = g_T1; c0 = col - 128; }
        else                { Asrc = g_T2; c0 = col - 256; }

        uint32_t sa = smem_u32 + (uint32_t)(s * STAGE_FLOATS) * 4u;
        uint32_t sb = sa + BM * BK * 4u;

#pragma unroll
        for (int j = 0; j < 2; j++) {
            int idx = tid + j * 256;
            int m = idx >> 3;
            int c = idx & 7;
            int node  = m0 + m;
            int bytes = (node < N_NODES) ? 16 : 0;
            int nd    = (node < N_NODES) ? node : 0;
            cp_async16(sa + (uint32_t)(m * BK + c * 4) * 4u,
                       Asrc + (size_t)nd * FDIM + c0 + c * 4, bytes);
        }
#pragma unroll
        for (int j = 0; j < 8; j++) {
            int idx  = tid + j * 256;
            int jr   = idx >> 6;
            int col4 = (idx & 63) * 4;
            const float* src = (col4 < 128)
                ? (Wz + (size_t)(col + jr) * 128 + col4)
                : (Wh + (size_t)(col + jr) * 128 + (col4 - 128));
            cp_async16(sb + (uint32_t)(jr * 256 + col4) * 4u, src, 16);
        }
        asm volatile("cp.async.commit_group;" ::: "memory");
    };

    load_stage(0, 0);

    for (int kb = 0; kb < NKB; kb++) {
        int s = kb & 1;
        if (kb + 1 < NKB) {
            load_stage(kb + 1, s ^ 1);
            asm volatile("cp.async.wait_group 1;" ::: "memory");
        } else {
            asm volatile("cp.async.wait_group 0;" ::: "memory");
        }
        __syncthreads();

        const float* A = smem + s * STAGE_FLOATS;
        const float* B = A + BM * BK;

#pragma unroll
        for (int k = 0; k < BK; k++) {
            // broadcast a[r] into both lanes of a 64-bit pack
            unsigned long long a2[4];
#pragma unroll
            for (int r = 0; r < 4; r++) {
                float av = A[(ty * 4 + r) * BK + k];
                asm("mov.b64 %0, {%1, %1};" : "=l"(a2[r]) : "f"(av));
            }

            // B pairs: adjacent columns are contiguous in smem
            const unsigned long long* Bz =
                (const unsigned long long*)(B + k * 256 + tx * 8);
            const unsigned long long* Bh =
                (const unsigned long long*)(B + k * 256 + 128 + tx * 8);
            unsigned long long bz[4] = {Bz[0], Bz[1], Bz[2], Bz[3]};
            unsigned long long bh[4] = {Bh[0], Bh[1], Bh[2], Bh[3]};

#pragma unroll
            for (int r = 0; r < 4; r++) {
#pragma unroll
                for (int i = 0; i < 4; i++) {
                    FMA2(czp[r][i], a2[r], bz[i], czp[r][i]);
                    FMA2(chp[r][i], a2[r], bh[i], chp[r][i]);
                }
            }
        }
        __syncthreads();
    }

    // ---- gate epilogue: Hn into smem ----
    float* Hs = smem;            // [BM][130]
#pragma unroll
    for (int i = 0; i < 4; i++) {
#pragma unroll
        for (int p = 0; p < 2; p++) {
            int h = tx * 8 + i * 2 + p;
            float bzs = bz0[h] + bz1[h];
            float bhs = bh0[h] + bh1[h];
#pragma unroll
            for (int r = 0; r < 4; r++) {
                int m = ty * 4 + r;
                float zlo, zhi, hlo, hhi;
                asm("mov.b64 {%0, %1}, %2;" : "=f"(zlo), "=f"(zhi) : "l"(czp[r][i]));
                asm("mov.b64 {%0, %1}, %2;" : "=f"(hlo), "=f"(hhi) : "l"(chp[r][i]));
                float z  = (p == 0 ? zlo : zhi) + bzs;
                float hp = (p == 0 ? hlo : hhi) + bhs;
                float sig = 1.f / (1.f + __expf(-z));
                Hs[m * 130 + h] = (1.f - sig) * tanhf(hp);
            }
        }
    }
    __syncthreads();

    // ---- output projection ----
    for (int idx = tid; idx < BM * TDIM; idx += 256) {
        int m = idx / TDIM;
        int t = idx % TDIM;
        int node = m0 + m;
        if (node < N_NODES) {
            float acc = blin[t];
            const float* hrow = Hs + m * 130;
#pragma unroll 16
            for (int h = 0; h < HDIM; h++)
                acc += hrow[h] * Wlin[h * TDIM + t];
            out[(size_t)node * TDIM + t] = acc;
        }
    }
}

// ---------------------------------------------------------------------------
// Launch
// ---------------------------------------------------------------------------
extern "C" void kernel_launch(void* const* d_in, const int* in_sizes, int n_in,
                              void* d_out, int out_size) {
    const float* x    = (const float*)d_in[0];
    const int*   ei   = (const int*)d_in[1];      // int32 (JAX x64 disabled)
    const float* ew   = (const float*)d_in[2];
    const float* Wxz  = (const float*)d_in[3];
    const float* bxz  = (const float*)d_in[4];
    const float* bhz  = (const float*)d_in[6];
    const float* Wxh  = (const float*)d_in[11];
    const float* bxh  = (const float*)d_in[12];
    const float* bhh  = (const float*)d_in[14];
    const float* Wlin = (const float*)d_in[15];
    const float* blin = (const float*)d_in[16];
    float*       out  = (float*)d_out;

    const int smem_bytes = 2 * STAGE_FLOATS * sizeof(float);
    cudaFuncSetAttribute(fused_kernel,
                         cudaFuncAttributeMaxDynamicSharedMemorySize, smem_bytes);

    // CSR build
    init_kernel<<<(N_NODES + 255) / 256, 256>>>();
    deg_kernel<<<(N_EDGES + 255) / 256, 256>>>(ei, ew);
    dinv_kernel<<<(N_NODES + 255) / 256, 256>>>();
    norm_kernel<<<(N_EDGES + 255) / 256, 256>>>(ei, ew);
    scan_kernel<<<1, SCAN_THREADS>>>();
    scatter_kernel<<<(N_EDGES + 255) / 256, 256>>>(ei);

    // Gather-side propagation: one warp per node
    const int PROP_BLOCKS = (N_NODES * 32 + 255) / 256;
    prop1_csr_kernel<<<PROP_BLOCKS, 256>>>(x);
    prop2_csr_kernel<<<PROP_BLOCKS, 256>>>(x);

    fused_kernel<<<(N_NODES + BM - 1) / BM, 256, smem_bytes>>>(
        x, Wxz, Wxh, bxz, bhz, bxh, bhh, Wlin, blin, out);
}

// round 9
// speedup vs baseline: 1.1237x; 1.1237x over previous
#include <cuda_runtime.h>
#include <cstdint>

#define N_NODES 50000
#define N_EDGES 800000
#define FDIM    128
#define HDIM    128
#define TDIM    10

// Scratch (device globals) — only ever referenced from DEVICE code.
__device__ __align__(16) float g_dinv[N_NODES];
__device__ int  g_cnt[N_NODES];
__device__ int  g_rowptr[N_NODES];
__device__ int  g_cursor[N_NODES];
__device__ __align__(16) int2  g_edges[N_EDGES];   // (src, norm bits), grouped by dst
__device__ __align__(16) float g_T1[N_NODES * FDIM];
__device__ __align__(16) float g_T2[N_NODES * FDIM];

// ---------------------------------------------------------------------------
// Stage 0: zero degree / per-dst count
// ---------------------------------------------------------------------------
__global__ void init_kernel() {
    int n = blockIdx.x * blockDim.x + threadIdx.x;
    if (n < N_NODES) { g_dinv[n] = 0.f; g_cnt[n] = 0; }
}

// Stage 1: deg[src] += w ; cnt[dst] += 1        (edge_index is int32)
__global__ void deg_kernel(const int* __restrict__ ei,
                           const float* __restrict__ ew) {
    int e = blockIdx.x * blockDim.x + threadIdx.x;
    if (e < N_EDGES) {
        atomicAdd(&g_dinv[ei[e]], ew[e]);
        atomicAdd(&g_cnt[ei[N_EDGES + e]], 1);
    }
}

// ---------------------------------------------------------------------------
// Stage 2: scan_kernel = dinv transform + brute-force exclusive scan
// ---------------------------------------------------------------------------
#define SCAN_THREADS 1024
#define SCAN_CHUNK   ((N_NODES + SCAN_THREADS - 1) / SCAN_THREADS)   // 49

__global__ void scan_kernel() {
    __shared__ int psum[SCAN_THREADS];
    const int tid = threadIdx.x;
    const int lo  = tid * SCAN_CHUNK;
    const int hi  = min(lo + SCAN_CHUNK, N_NODES);

    int s = 0;
    for (int i = lo; i < hi; i++) {
        s += g_cnt[i];
        float d = g_dinv[i];
        g_dinv[i] = (d > 0.f) ? rsqrtf(d) : 0.f;   // fused dinv
    }
    psum[tid] = s;
    __syncthreads();

    if (tid == 0) {
        int running = 0;
        for (int i = 0; i < SCAN_THREADS; i++) {
            int t = psum[i];
            psum[i] = running;
            running += t;
        }
    }
    __syncthreads();

    int base = psum[tid];
    for (int i = lo; i < hi; i++) {
        g_rowptr[i] = base;
        g_cursor[i] = base;
        base += g_cnt[i];
    }
}

// Stage 3: scatter packed (src, norm) into dst-grouped CSR slots (norm inline)
__global__ void scatter_kernel(const int* __restrict__ ei,
                               const float* __restrict__ ew) {
    int e = blockIdx.x * blockDim.x + threadIdx.x;
    if (e < N_EDGES) {
        int s = ei[e];
        int d = ei[N_EDGES + e];
        float nrm = -g_dinv[s] * ew[e] * g_dinv[d];
        int pos = atomicAdd(&g_cursor[d], 1);
        g_edges[pos] = make_int2(s, __float_as_int(nrm));
    }
}

// ---------------------------------------------------------------------------
// Stage 4/5: gather-side propagation, one warp per dst node (unroll x2).
// ---------------------------------------------------------------------------
__global__ void prop1_csr_kernel(const float* __restrict__ x) {
    int node = (blockIdx.x * blockDim.x + threadIdx.x) >> 5;
    int lane = threadIdx.x & 31;
    if (node >= N_NODES) return;
    int base = g_rowptr[node];
    int cnt  = g_cnt[node];

    float4 acc = make_float4(0.f, 0.f, 0.f, 0.f);
    int j = 0;
    for (; j + 2 <= cnt; j += 2) {
        int2 e0 = g_edges[base + j];
        int2 e1 = g_edges[base + j + 1];
        float w0 = __int_as_float(e0.y);
        float w1 = __int_as_float(e1.y);
        float4 v0 = ((const float4*)(x + (size_t)e0.x * FDIM))[lane];
        float4 v1 = ((const float4*)(x + (size_t)e1.x * FDIM))[lane];
        acc.x += w0 * v0.x; acc.y += w0 * v0.y;
        acc.z += w0 * v0.z; acc.w += w0 * v0.w;
        acc.x += w1 * v1.x; acc.y += w1 * v1.y;
        acc.z += w1 * v1.z; acc.w += w1 * v1.w;
    }
    if (j < cnt) {
        int2 e0 = g_edges[base + j];
        float w0 = __int_as_float(e0.y);
        float4 v0 = ((const float4*)(x + (size_t)e0.x * FDIM))[lane];
        acc.x += w0 * v0.x; acc.y += w0 * v0.y;
        acc.z += w0 * v0.z; acc.w += w0 * v0.w;
    }
    ((float4*)(g_T1 + (size_t)node * FDIM))[lane] = acc;
}

__global__ void prop2_csr_kernel(const float* __restrict__ x) {
    int node = (blockIdx.x * blockDim.x + threadIdx.x) >> 5;
    int lane = threadIdx.x & 31;
    if (node >= N_NODES) return;
    int base = g_rowptr[node];
    int cnt  = g_cnt[node];

    float4 acc = make_float4(0.f, 0.f, 0.f, 0.f);
    int j = 0;
    for (; j + 2 <= cnt; j += 2) {
        int2 e0 = g_edges[base + j];
        int2 e1 = g_edges[base + j + 1];
        float w0 = __int_as_float(e0.y);
        float w1 = __int_as_float(e1.y);
        float4 v0 = ((const float4*)(g_T1 + (size_t)e0.x * FDIM))[lane];
        float4 v1 = ((const float4*)(g_T1 + (size_t)e1.x * FDIM))[lane];
        acc.x += w0 * v0.x; acc.y += w0 * v0.y;
        acc.z += w0 * v0.z; acc.w += w0 * v0.w;
        acc.x += w1 * v1.x; acc.y += w1 * v1.y;
        acc.z += w1 * v1.z; acc.w += w1 * v1.w;
    }
    if (j < cnt) {
        int2 e0 = g_edges[base + j];
        float w0 = __int_as_float(e0.y);
        float4 v0 = ((const float4*)(g_T1 + (size_t)e0.x * FDIM))[lane];
        acc.x += w0 * v0.x; acc.y += w0 * v0.y;
        acc.z += w0 * v0.z; acc.w += w0 * v0.w;
    }
    float4 xx = ((const float4*)(x + (size_t)node * FDIM))[lane];
    acc.x = 2.f * acc.x - xx.x;
    acc.y = 2.f * acc.y - xx.y;
    acc.z = 2.f * acc.z - xx.z;
    acc.w = 2.f * acc.w - xx.w;
    ((float4*)(g_T2 + (size_t)node * FDIM))[lane] = acc;
}

// ---------------------------------------------------------------------------
// Stage 6: fused GEMM + gate epilogue + output projection
// BM=128, BK=16; each thread: 8 rows x 16 cols (8 z + 8 h) -> 0.75 smem B/FLOP
// ---------------------------------------------------------------------------
#define BM  128
#define BK  16
#define NKB 24
#define STAGE_FLOATS (BM*BK + BK*256)        // 2048 + 4096 = 6144
#define HS_STRIDE 129
#define HS_FLOATS (BM * HS_STRIDE)           // 16512
#define WLT_OFF   HS_FLOATS                  // WlinT at smem[16512..17792)
#define SMEM_FLOATS_TOTAL (HS_FLOATS + TDIM * HDIM)   // 17792

extern __shared__ float smem[];

__device__ __forceinline__ void cp_async16(uint32_t saddr, const float* g, int bytes) {
    asm volatile("cp.async.cg.shared.global [%0], [%1], 16, %2;"
                 :: "r"(saddr), "l"(g), "r"(bytes) : "memory");
}

#define FMA2(d, a, b, c) \
    asm("fma.rn.f32x2 %0, %1, %2, %3;" : "=l"(d) : "l"(a), "l"(b), "l"(c))

__global__ __launch_bounds__(256, 1) void fused_kernel(
    const float* __restrict__ x,
    const float* __restrict__ Wz, const float* __restrict__ Wh,
    const float* __restrict__ bz0, const float* __restrict__ bz1,
    const float* __restrict__ bh0, const float* __restrict__ bh1,
    const float* __restrict__ Wlin, const float* __restrict__ blin,
    float* __restrict__ out)
{
    const int tid = threadIdx.x;
    const int tx  = tid & 15;
    const int ty  = tid >> 4;
    const int m0  = blockIdx.x * BM;

    const uint32_t smem_u32 = (uint32_t)__cvta_generic_to_shared(smem);

    unsigned long long czp[8][4];
    unsigned long long chp[8][4];
#pragma unroll
    for (int r = 0; r < 8; r++)
#pragma unroll
        for (int i = 0; i < 4; i++) { czp[r][i] = 0ULL; chp[r][i] = 0ULL; }

    auto load_stage = [&](int kb, int s) {
        const int col = kb * BK;
        const float* Asrc;
        int c0;
        if (col < 128)      { Asrc = x;    c0 = col; }
        else if (col < 256) { Asrc = g_T1; c0 = col - 128; }
        else                { Asrc = g_T2; c0 = col - 256; }

        uint32_t sa = smem_u32 + (uint32_t)(s * STAGE_FLOATS) * 4u;
        uint32_t sb = sa + BM * BK * 4u;

        // A tile: 128 rows x 16 floats = 512 float4 -> 2 per thread
#pragma unroll
        for (int j = 0; j < 2; j++) {
            int idx = tid + j * 256;
            int m = idx >> 2;
            int c = idx & 3;
            int node  = m0 + m;
            int bytes = (node < N_NODES) ? 16 : 0;
            int nd    = (node < N_NODES) ? node : 0;
            cp_async16(sa + (uint32_t)(m * BK + c * 4) * 4u,
                       Asrc + (size_t)nd * FDIM + c0 + c * 4, bytes);
        }
        // B tile: 16 rows x 256 floats = 1024 float4 -> 4 per thread
#pragma unroll
        for (int j = 0; j < 4; j++) {
            int idx  = tid + j * 256;
            int jr   = idx >> 6;
            int col4 = (idx & 63) * 4;
            const float* src = (col4 < 128)
                ? (Wz + (size_t)(col + jr) * 128 + col4)
                : (Wh + (size_t)(col + jr) * 128 + (col4 - 128));
            cp_async16(sb + (uint32_t)(jr * 256 + col4) * 4u, src, 16);
        }
        asm volatile("cp.async.commit_group;" ::: "memory");
    };

    load_stage(0, 0);

    for (int kb = 0; kb < NKB; kb++) {
        int s = kb & 1;
        if (kb + 1 < NKB) {
            load_stage(kb + 1, s ^ 1);
            asm volatile("cp.async.wait_group 1;" ::: "memory");
        } else {
            asm volatile("cp.async.wait_group 0;" ::: "memory");
        }
        __syncthreads();

        const float* A = smem + s * STAGE_FLOATS;
        const float* B = A + BM * BK;

#pragma unroll
        for (int k = 0; k < BK; k++) {
            unsigned long long a2[8];
#pragma unroll
            for (int r = 0; r < 8; r++) {
                float av = A[(ty * 8 + r) * BK + k];
                asm("mov.b64 %0, {%1, %1};" : "=l"(a2[r]) : "f"(av));
            }

            const unsigned long long* Bz =
                (const unsigned long long*)(B + k * 256 + tx * 8);
            const unsigned long long* Bh =
                (const unsigned long long*)(B + k * 256 + 128 + tx * 8);
            unsigned long long bz[4] = {Bz[0], Bz[1], Bz[2], Bz[3]};
            unsigned long long bh[4] = {Bh[0], Bh[1], Bh[2], Bh[3]};

#pragma unroll
            for (int r = 0; r < 8; r++) {
#pragma unroll
                for (int i = 0; i < 4; i++) {
                    FMA2(czp[r][i], a2[r], bz[i], czp[r][i]);
                    FMA2(chp[r][i], a2[r], bh[i], chp[r][i]);
                }
            }
        }
        __syncthreads();
    }

    // ---- gate epilogue: Hn into smem [BM][129] ----
    float* Hs = smem;
#pragma unroll
    for (int i = 0; i < 4; i++) {
#pragma unroll
        for (int p = 0; p < 2; p++) {
            int h = tx * 8 + i * 2 + p;
            float bzs = bz0[h] + bz1[h];
            float bhs = bh0[h] + bh1[h];
#pragma unroll
            for (int r = 0; r < 8; r++) {
                int m = ty * 8 + r;
                float zlo, zhi, hlo, hhi;
                asm("mov.b64 {%0, %1}, %2;" : "=f"(zlo), "=f"(zhi) : "l"(czp[r][i]));
                asm("mov.b64 {%0, %1}, %2;" : "=f"(hlo), "=f"(hhi) : "l"(chp[r][i]));
                float z  = (p == 0 ? zlo : zhi) + bzs;
                float hp = (p == 0 ? hlo : hhi) + bhs;
                float sig = 1.f / (1.f + __expf(-z));
                Hs[m * HS_STRIDE + h] = (1.f - sig) * tanhf(hp);
            }
        }
    }

    // ---- stage Wlin transposed: WlinT[t*128+h] = Wlin[h*10+t] ----
    float* WlinT = smem + WLT_OFF;
    for (int idx = tid; idx < TDIM * HDIM; idx += 256) {
        int t = idx % TDIM;
        int h = idx / TDIM;
        WlinT[t * HDIM + h] = Wlin[h * TDIM + t];
    }
    __syncthreads();

    // ---- output projection: thread = (row m, half g); 5 t's per thread ----
    {
        int m = tid >> 1;
        int g = tid & 1;
        int node = m0 + m;
        if (node < N_NODES) {
            float acc[5];
#pragma unroll
            for (int j = 0; j < 5; j++) acc[j] = blin[g * 5 + j];
            const float* hrow = Hs + m * HS_STRIDE;
#pragma unroll 8
            for (int h = 0; h < HDIM; h++) {
                float v = hrow[h];
#pragma unroll
                for (int j = 0; j < 5; j++)
                    acc[j] += v * WlinT[(g * 5 + j) * HDIM + h];
            }
#pragma unroll
            for (int j = 0; j < 5; j++)
                out[(size_t)node * TDIM + g * 5 + j] = acc[j];
        }
    }
}

// ---------------------------------------------------------------------------
// Launch
// ---------------------------------------------------------------------------
extern "C" void kernel_launch(void* const* d_in, const int* in_sizes, int n_in,
                              void* d_out, int out_size) {
    const float* x    = (const float*)d_in[0];
    const int*   ei   = (const int*)d_in[1];      // int32 (JAX x64 disabled)
    const float* ew   = (const float*)d_in[2];
    const float* Wxz  = (const float*)d_in[3];
    const float* bxz  = (const float*)d_in[4];
    const float* bhz  = (const float*)d_in[6];
    const float* Wxh  = (const float*)d_in[11];
    const float* bxh  = (const float*)d_in[12];
    const float* bhh  = (const float*)d_in[14];
    const float* Wlin = (const float*)d_in[15];
    const float* blin = (const float*)d_in[16];
    float*       out  = (float*)d_out;

    const int smem_bytes = SMEM_FLOATS_TOTAL * sizeof(float);   // 71168
    cudaFuncSetAttribute(fused_kernel,
                         cudaFuncAttributeMaxDynamicSharedMemorySize, smem_bytes);

    // CSR build (dinv folded into scan; norm folded into scatter)
    init_kernel<<<(N_NODES + 255) / 256, 256>>>();
    deg_kernel<<<(N_EDGES + 255) / 256, 256>>>(ei, ew);
    scan_kernel<<<1, SCAN_THREADS>>>();
    scatter_kernel<<<(N_EDGES + 255) / 256, 256>>>(ei, ew);

    // Gather-side propagation: one warp per node
    const int PROP_BLOCKS = (N_NODES * 32 + 255) / 256;
    prop1_csr_kernel<<<PROP_BLOCKS, 256>>>(x);
    prop2_csr_kernel<<<PROP_BLOCKS, 256>>>(x);

    fused_kernel<<<(N_NODES + BM - 1) / BM, 256, smem_bytes>>>(
        x, Wxz, Wxh, bxz, bhz, bxh, bhh, Wlin, blin, out);
}

// round 10
// speedup vs baseline: 1.1586x; 1.0310x over previous
#include <cuda_runtime.h>
#include <cstdint>

#define N_NODES 50000
#define N_EDGES 800000
#define FDIM    128
#define HDIM    128
#define TDIM    10

// Scratch (device globals) — only ever referenced from DEVICE code.
__device__ __align__(16) float g_dinv[N_NODES];
__device__ int  g_cnt[N_NODES];
__device__ int  g_rowptr[N_NODES];
__device__ int  g_cursor[N_NODES];
__device__ __align__(16) int2  g_edges[N_EDGES];   // (src, norm bits), grouped by dst
__device__ __align__(16) float g_T1[N_NODES * FDIM];
__device__ __align__(16) float g_T2[N_NODES * FDIM];

// ---------------------------------------------------------------------------
// Stage 0: zero degree / per-dst count
// ---------------------------------------------------------------------------
__global__ void init_kernel() {
    int n = blockIdx.x * blockDim.x + threadIdx.x;
    if (n < N_NODES) { g_dinv[n] = 0.f; g_cnt[n] = 0; }
}

// Stage 1: deg[src] += w ; cnt[dst] += 1        (edge_index is int32)
__global__ void deg_kernel(const int* __restrict__ ei,
                           const float* __restrict__ ew) {
    int e = blockIdx.x * blockDim.x + threadIdx.x;
    if (e < N_EDGES) {
        atomicAdd(&g_dinv[ei[e]], ew[e]);
        atomicAdd(&g_cnt[ei[N_EDGES + e]], 1);
    }
}

// ---------------------------------------------------------------------------
// Stage 2: fused dinv transform + PARALLEL exclusive scan (warp-shfl)
// ---------------------------------------------------------------------------
#define SCAN_THREADS 1024
#define SCAN_CHUNK   ((N_NODES + SCAN_THREADS - 1) / SCAN_THREADS)   // 49

__global__ void scan_kernel() {
    __shared__ int wsum[32];
    const int tid  = threadIdx.x;
    const int lane = tid & 31;
    const int wid  = tid >> 5;
    const int lo   = tid * SCAN_CHUNK;
    const int hi   = min(lo + SCAN_CHUNK, N_NODES);

    int v = 0;
    for (int i = lo; i < hi; i++) {
        v += g_cnt[i];
        float d = g_dinv[i];
        g_dinv[i] = (d > 0.f) ? rsqrtf(d) : 0.f;   // fused dinv
    }

    // hierarchical inclusive scan of per-thread sums
    int inc = v;
#pragma unroll
    for (int o = 1; o < 32; o <<= 1) {
        int t = __shfl_up_sync(0xffffffffu, inc, o);
        if (lane >= o) inc += t;
    }
    if (lane == 31) wsum[wid] = inc;
    __syncthreads();
    if (wid == 0) {
        int t = wsum[lane];
#pragma unroll
        for (int o = 1; o < 32; o <<= 1) {
            int u = __shfl_up_sync(0xffffffffu, t, o);
            if (lane >= o) t += u;
        }
        wsum[lane] = t;
    }
    __syncthreads();

    int base = ((wid > 0) ? wsum[wid - 1] : 0) + inc - v;  // exclusive prefix
    for (int i = lo; i < hi; i++) {
        g_rowptr[i] = base;
        g_cursor[i] = base;
        base += g_cnt[i];
    }
}

// Stage 3: scatter packed (src, norm) into dst-grouped CSR slots (norm inline)
__global__ void scatter_kernel(const int* __restrict__ ei,
                               const float* __restrict__ ew) {
    int e = blockIdx.x * blockDim.x + threadIdx.x;
    if (e < N_EDGES) {
        int s = ei[e];
        int d = ei[N_EDGES + e];
        float nrm = -g_dinv[s] * ew[e] * g_dinv[d];
        int pos = atomicAdd(&g_cursor[d], 1);
        g_edges[pos] = make_int2(s, __float_as_int(nrm));
    }
}

// ---------------------------------------------------------------------------
// Stage 4/5: gather-side propagation, one warp per dst node (unroll x2).
// ---------------------------------------------------------------------------
__global__ void prop1_csr_kernel(const float* __restrict__ x) {
    int node = (blockIdx.x * blockDim.x + threadIdx.x) >> 5;
    int lane = threadIdx.x & 31;
    if (node >= N_NODES) return;
    int base = g_rowptr[node];
    int cnt  = g_cnt[node];

    float4 acc = make_float4(0.f, 0.f, 0.f, 0.f);
    int j = 0;
    for (; j + 2 <= cnt; j += 2) {
        int2 e0 = g_edges[base + j];
        int2 e1 = g_edges[base + j + 1];
        float w0 = __int_as_float(e0.y);
        float w1 = __int_as_float(e1.y);
        float4 v0 = ((const float4*)(x + (size_t)e0.x * FDIM))[lane];
        float4 v1 = ((const float4*)(x + (size_t)e1.x * FDIM))[lane];
        acc.x += w0 * v0.x; acc.y += w0 * v0.y;
        acc.z += w0 * v0.z; acc.w += w0 * v0.w;
        acc.x += w1 * v1.x; acc.y += w1 * v1.y;
        acc.z += w1 * v1.z; acc.w += w1 * v1.w;
    }
    if (j < cnt) {
        int2 e0 = g_edges[base + j];
        float w0 = __int_as_float(e0.y);
        float4 v0 = ((const float4*)(x + (size_t)e0.x * FDIM))[lane];
        acc.x += w0 * v0.x; acc.y += w0 * v0.y;
        acc.z += w0 * v0.z; acc.w += w0 * v0.w;
    }
    ((float4*)(g_T1 + (size_t)node * FDIM))[lane] = acc;
}

__global__ void prop2_csr_kernel(const float* __restrict__ x) {
    int node = (blockIdx.x * blockDim.x + threadIdx.x) >> 5;
    int lane = threadIdx.x & 31;
    if (node >= N_NODES) return;
    int base = g_rowptr[node];
    int cnt  = g_cnt[node];

    float4 acc = make_float4(0.f, 0.f, 0.f, 0.f);
    int j = 0;
    for (; j + 2 <= cnt; j += 2) {
        int2 e0 = g_edges[base + j];
        int2 e1 = g_edges[base + j + 1];
        float w0 = __int_as_float(e0.y);
        float w1 = __int_as_float(e1.y);
        float4 v0 = ((const float4*)(g_T1 + (size_t)e0.x * FDIM))[lane];
        float4 v1 = ((const float4*)(g_T1 + (size_t)e1.x * FDIM))[lane];
        acc.x += w0 * v0.x; acc.y += w0 * v0.y;
        acc.z += w0 * v0.z; acc.w += w0 * v0.w;
        acc.x += w1 * v1.x; acc.y += w1 * v1.y;
        acc.z += w1 * v1.z; acc.w += w1 * v1.w;
    }
    if (j < cnt) {
        int2 e0 = g_edges[base + j];
        float w0 = __int_as_float(e0.y);
        float4 v0 = ((const float4*)(g_T1 + (size_t)e0.x * FDIM))[lane];
        acc.x += w0 * v0.x; acc.y += w0 * v0.y;
        acc.z += w0 * v0.z; acc.w += w0 * v0.w;
    }
    float4 xx = ((const float4*)(x + (size_t)node * FDIM))[lane];
    acc.x = 2.f * acc.x - xx.x;
    acc.y = 2.f * acc.y - xx.y;
    acc.z = 2.f * acc.z - xx.z;
    acc.w = 2.f * acc.w - xx.w;
    ((float4*)(g_T2 + (size_t)node * FDIM))[lane] = acc;
}

// ---------------------------------------------------------------------------
// Stage 6: fused GEMM (tensor cores, 3xTF32) + gate + output projection
//   A (virtual) = [x | T1 | T2] : 50000 x 384 fp32
//   BM=64, BN=256 (128 z + 128 h), BK=16, 8 warps (2M x 4N), warp tile 32x64
//   D = Ab*Bb + Ab*dB + dA*Bb  (3xTF32: fp32-grade accuracy)
// ---------------------------------------------------------------------------
#define BM   64
#define BKT  16
#define NKB  24                       // 384 / 16
#define A_STRIDE 17
#define B_STRIDE 260
#define A_FLOATS (BM * A_STRIDE)      // 1088
#define STG_FLOATS (A_FLOATS + BKT * B_STRIDE)   // 1088 + 4160 = 5248
#define ZB_STRIDE 132
#define ZBUF_OFF  0
#define HBUF_OFF  (BM * ZB_STRIDE)               // 8448
#define WLT_OFF   (2 * BM * ZB_STRIDE)           // 16896
#define BZS_OFF   (WLT_OFF + TDIM * HDIM)        // 18176
#define BHS_OFF   (BZS_OFF + HDIM)               // 18304
#define SMEM_FLOATS_TOTAL (BHS_OFF + HDIM)       // 18432 -> 73728 B

extern __shared__ float smem[];

__device__ __forceinline__ void cp_async16(uint32_t saddr, const float* g, int bytes) {
    asm volatile("cp.async.cg.shared.global [%0], [%1], 16, %2;"
                 :: "r"(saddr), "l"(g), "r"(bytes) : "memory");
}
__device__ __forceinline__ void cp_async4(uint32_t saddr, const float* g, int bytes) {
    asm volatile("cp.async.ca.shared.global [%0], [%1], 4, %2;"
                 :: "r"(saddr), "l"(g), "r"(bytes) : "memory");
}

__device__ __forceinline__ uint32_t f2tf32(float v) {
    uint32_t o;
    asm("cvt.rna.tf32.f32 %0, %1;" : "=r"(o) : "f"(v));
    return o;
}

__device__ __forceinline__ void mma_tf32(float* c, const uint32_t* a, const uint32_t* b) {
    asm volatile(
        "mma.sync.aligned.m16n8k8.row.col.f32.tf32.tf32.f32 "
        "{%0,%1,%2,%3}, {%4,%5,%6,%7}, {%8,%9}, {%0,%1,%2,%3};"
        : "+f"(c[0]), "+f"(c[1]), "+f"(c[2]), "+f"(c[3])
        : "r"(a[0]), "r"(a[1]), "r"(a[2]), "r"(a[3]),
          "r"(b[0]), "r"(b[1]));
}

__global__ __launch_bounds__(256, 1) void fused_kernel(
    const float* __restrict__ x,
    const float* __restrict__ Wz, const float* __restrict__ Wh,
    const float* __restrict__ bz0, const float* __restrict__ bz1,
    const float* __restrict__ bh0, const float* __restrict__ bh1,
    const float* __restrict__ Wlin, const float* __restrict__ blin,
    float* __restrict__ out)
{
    const int tid  = threadIdx.x;
    const int lane = tid & 31;
    const int wid  = tid >> 5;
    const int wm   = wid & 1;          // 2 M-blocks of 32
    const int wn   = wid >> 1;         // 4 N-blocks of 64
    const int mwb  = wm * 32;
    const int nwb  = wn * 64;
    const int m0   = blockIdx.x * BM;

    const uint32_t smem_u32 = (uint32_t)__cvta_generic_to_shared(smem);

    float c[2][8][4];
#pragma unroll
    for (int mi = 0; mi < 2; mi++)
#pragma unroll
        for (int ni = 0; ni < 8; ni++)
#pragma unroll
            for (int q = 0; q < 4; q++) c[mi][ni][q] = 0.f;

    auto load_stage = [&](int kb, int s) {
        const int col = kb * BKT;
        const float* Asrc;
        int c0;
        if (col < 128)      { Asrc = x;    c0 = col; }
        else if (col < 256) { Asrc = g_T1; c0 = col - 128; }
        else                { Asrc = g_T2; c0 = col - 256; }

        uint32_t sa = smem_u32 + (uint32_t)(s * STG_FLOATS) * 4u;
        uint32_t sb = sa + (uint32_t)A_FLOATS * 4u;

        // A tile: 64 rows x 16 k = 1024 floats -> 4 per thread (4B cp.async)
#pragma unroll
        for (int j = 0; j < 4; j++) {
            int idx = tid + j * 256;
            int m = idx >> 4;
            int k = idx & 15;
            int node  = m0 + m;
            int bytes = (node < N_NODES) ? 4 : 0;
            int nd    = (node < N_NODES) ? node : 0;
            cp_async4(sa + (uint32_t)(m * A_STRIDE + k) * 4u,
                      Asrc + (size_t)nd * FDIM + c0 + k, bytes);
        }
        // B tile: 16 k-rows x 256 cols = 1024 float4 -> 4 per thread
#pragma unroll
        for (int j = 0; j < 4; j++) {
            int idx  = tid + j * 256;
            int jr   = idx >> 6;
            int col4 = (idx & 63) * 4;
            const float* src = (col4 < 128)
                ? (Wz + (size_t)(col + jr) * 128 + col4)
                : (Wh + (size_t)(col + jr) * 128 + (col4 - 128));
            cp_async16(sb + (uint32_t)(jr * B_STRIDE + col4) * 4u, src, 16);
        }
        asm volatile("cp.async.commit_group;" ::: "memory");
    };

    load_stage(0, 0);

    const int ar = lane >> 2;     // 0..7
    const int ac = lane & 3;      // 0..3

    for (int kb = 0; kb < NKB; kb++) {
        int s = kb & 1;
        if (kb + 1 < NKB) {
            load_stage(kb + 1, s ^ 1);
            asm volatile("cp.async.wait_group 1;" ::: "memory");
        } else {
            asm volatile("cp.async.wait_group 0;" ::: "memory");
        }
        __syncthreads();

        const float* A = smem + s * STG_FLOATS;
        const float* B = A + A_FLOATS;

#pragma unroll
        for (int k8 = 0; k8 < 2; k8++) {
            const int kk = k8 * 8;

            // A fragments (2 m16 blocks), 3x split
            uint32_t ab[2][4], ad[2][4];
#pragma unroll
            for (int mi = 0; mi < 2; mi++) {
                int r0 = mwb + mi * 16 + ar;
                float v0 = A[r0 * A_STRIDE + kk + ac];
                float v1 = A[(r0 + 8) * A_STRIDE + kk + ac];
                float v2 = A[r0 * A_STRIDE + kk + ac + 4];
                float v3 = A[(r0 + 8) * A_STRIDE + kk + ac + 4];
                ab[mi][0] = f2tf32(v0); ad[mi][0] = f2tf32(v0 - __uint_as_float(ab[mi][0]));
                ab[mi][1] = f2tf32(v1); ad[mi][1] = f2tf32(v1 - __uint_as_float(ab[mi][1]));
                ab[mi][2] = f2tf32(v2); ad[mi][2] = f2tf32(v2 - __uint_as_float(ab[mi][2]));
                ab[mi][3] = f2tf32(v3); ad[mi][3] = f2tf32(v3 - __uint_as_float(ab[mi][3]));
            }

            // B fragments (8 n8 blocks), 3x split
            uint32_t bb[8][2], bd[8][2];
#pragma unroll
            for (int ni = 0; ni < 8; ni++) {
                int br = kk + ac;
                int bc = nwb + ni * 8 + ar;
                float u0 = B[br * B_STRIDE + bc];
                float u1 = B[(br + 4) * B_STRIDE + bc];
                bb[ni][0] = f2tf32(u0); bd[ni][0] = f2tf32(u0 - __uint_as_float(bb[ni][0]));
                bb[ni][1] = f2tf32(u1); bd[ni][1] = f2tf32(u1 - __uint_as_float(bb[ni][1]));
            }

#pragma unroll
            for (int mi = 0; mi < 2; mi++) {
#pragma unroll
                for (int ni = 0; ni < 8; ni++) {
                    mma_tf32(c[mi][ni], ab[mi], bb[ni]);   // big*big
                    mma_tf32(c[mi][ni], ab[mi], bd[ni]);   // big*dB
                    mma_tf32(c[mi][ni], ad[mi], bb[ni]);   // dA*big
                }
            }
        }
        __syncthreads();
    }

    // ---- write accumulators to zbuf/hbuf ----
    float* zbuf = smem + ZBUF_OFF;   // [64][132]
    float* hbuf = smem + HBUF_OFF;   // [64][132]
#pragma unroll
    for (int mi = 0; mi < 2; mi++) {
#pragma unroll
        for (int ni = 0; ni < 8; ni++) {
            int m = mwb + mi * 16 + ar;
            int n = nwb + ni * 8 + ac * 2;
            float* buf = (n < 128) ? (zbuf + n) : (hbuf + n - 128);
            buf[m * ZB_STRIDE]           = c[mi][ni][0];
            buf[m * ZB_STRIDE + 1]       = c[mi][ni][1];
            buf[(m + 8) * ZB_STRIDE]     = c[mi][ni][2];
            buf[(m + 8) * ZB_STRIDE + 1] = c[mi][ni][3];
        }
    }

    // stage bias sums + WlinT (disjoint smem regions)
    float* WlinT = smem + WLT_OFF;
    float* bzs   = smem + BZS_OFF;
    float* bhs   = smem + BHS_OFF;
    if (tid < 128) {
        bzs[tid] = bz0[tid] + bz1[tid];
        bhs[tid] = bh0[tid] + bh1[tid];
    }
    for (int idx = tid; idx < TDIM * HDIM; idx += 256) {
        int t = idx % TDIM;
        int h = idx / TDIM;
        WlinT[t * HDIM + h] = Wlin[h * TDIM + t];
    }
    __syncthreads();

    // ---- gate: Hn = (1-sigmoid(z)) * tanh(h) into zbuf in place ----
    for (int idx = tid; idx < BM * HDIM; idx += 256) {
        int m = idx >> 7;
        int h = idx & 127;
        float z  = zbuf[m * ZB_STRIDE + h] + bzs[h];
        float hp = hbuf[m * ZB_STRIDE + h] + bhs[h];
        float sig = 1.f / (1.f + __expf(-z));
        zbuf[m * ZB_STRIDE + h] = (1.f - sig) * tanhf(hp);
    }
    __syncthreads();

    // ---- output projection: thread = (row m, half g); 5 t's per thread ----
    if (tid < 2 * BM) {
        int m = tid >> 1;
        int g = tid & 1;
        int node = m0 + m;
        if (node < N_NODES) {
            float acc[5];
#pragma unroll
            for (int j = 0; j < 5; j++) acc[j] = blin[g * 5 + j];
            const float* hrow = zbuf + m * ZB_STRIDE;
#pragma unroll 8
            for (int h = 0; h < HDIM; h++) {
                float v = hrow[h];
#pragma unroll
                for (int j = 0; j < 5; j++)
                    acc[j] += v * WlinT[(g * 5 + j) * HDIM + h];
            }
#pragma unroll
            for (int j = 0; j < 5; j++)
                out[(size_t)node * TDIM + g * 5 + j] = acc[j];
        }
    }
}

// ---------------------------------------------------------------------------
// Launch
// ---------------------------------------------------------------------------
extern "C" void kernel_launch(void* const* d_in, const int* in_sizes, int n_in,
                              void* d_out, int out_size) {
    const float* x    = (const float*)d_in[0];
    const int*   ei   = (const int*)d_in[1];      // int32 (JAX x64 disabled)
    const float* ew   = (const float*)d_in[2];
    const float* Wxz  = (const float*)d_in[3];
    const float* bxz  = (const float*)d_in[4];
    const float* bhz  = (const float*)d_in[6];
    const float* Wxh  = (const float*)d_in[11];
    const float* bxh  = (const float*)d_in[12];
    const float* bhh  = (const float*)d_in[14];
    const float* Wlin = (const float*)d_in[15];
    const float* blin = (const float*)d_in[16];
    float*       out  = (float*)d_out;

    const int smem_bytes = SMEM_FLOATS_TOTAL * sizeof(float);   // 73728
    cudaFuncSetAttribute(fused_kernel,
                         cudaFuncAttributeMaxDynamicSharedMemorySize, smem_bytes);

    // CSR build
    init_kernel<<<(N_NODES + 255) / 256, 256>>>();
    deg_kernel<<<(N_EDGES + 255) / 256, 256>>>(ei, ew);
    scan_kernel<<<1, SCAN_THREADS>>>();
    scatter_kernel<<<(N_EDGES + 255) / 256, 256>>>(ei, ew);

    // Gather-side propagation: one warp per node
    const int PROP_BLOCKS = (N_NODES * 32 + 255) / 256;
    prop1_csr_kernel<<<PROP_BLOCKS, 256>>>(x);
    prop2_csr_kernel<<<PROP_BLOCKS, 256>>>(x);

    fused_kernel<<<(N_NODES + BM - 1) / BM, 256, smem_bytes>>>(
        x, Wxz, Wxh, bxz, bhz, bxh, bhh, Wlin, blin, out);
}

// round 11
// speedup vs baseline: 1.2206x; 1.0536x over previous
#include <cuda_runtime.h>
#include <cstdint>

#define N_NODES 50000
#define N_EDGES 800000
#define FDIM    128
#define HDIM    128
#define TDIM    10

// Scratch (device globals) — only ever referenced from DEVICE code.
__device__ __align__(16) float g_dinv[N_NODES];
__device__ int  g_cnt[N_NODES];
__device__ int  g_rowptr[N_NODES];
__device__ int  g_cursor[N_NODES];
__device__ __align__(16) int2  g_edges[N_EDGES];
__device__ __align__(16) float g_T1[N_NODES * FDIM];
__device__ __align__(16) float g_T2[N_NODES * FDIM];
// Pre-split B operand (tf32 big + delta), concatenated layout [384][256] = [k][z|h]
__device__ __align__(16) uint32_t g_Bb[384 * 256];
__device__ __align__(16) uint32_t g_Bd[384 * 256];

__device__ __forceinline__ uint32_t f2tf32(float v) {
    uint32_t o;
    asm("cvt.rna.tf32.f32 %0, %1;" : "=r"(o) : "f"(v));
    return o;
}

// ---------------------------------------------------------------------------
// Stage 0a: pre-split weights into tf32 big/delta (loop-invariant work hoist)
// ---------------------------------------------------------------------------
__global__ void split_kernel(const float* __restrict__ Wz,
                             const float* __restrict__ Wh) {
    int idx = blockIdx.x * blockDim.x + threadIdx.x;
    if (idx < 384 * 256) {
        int k = idx >> 8;
        int c = idx & 255;
        float v = (c < 128) ? Wz[k * 128 + c] : Wh[k * 128 + (c - 128)];
        uint32_t big = f2tf32(v);
        g_Bb[idx] = big;
        g_Bd[idx] = f2tf32(v - __uint_as_float(big));
    }
}

// Stage 0b: zero degree / per-dst count
__global__ void init_kernel() {
    int n = blockIdx.x * blockDim.x + threadIdx.x;
    if (n < N_NODES) { g_dinv[n] = 0.f; g_cnt[n] = 0; }
}

// Stage 1: deg[src] += w ; cnt[dst] += 1        (edge_index is int32)
__global__ void deg_kernel(const int* __restrict__ ei,
                           const float* __restrict__ ew) {
    int e = blockIdx.x * blockDim.x + threadIdx.x;
    if (e < N_EDGES) {
        atomicAdd(&g_dinv[ei[e]], ew[e]);
        atomicAdd(&g_cnt[ei[N_EDGES + e]], 1);
    }
}

// ---------------------------------------------------------------------------
// Stage 2: fused dinv transform + parallel exclusive scan (warp-shfl)
// ---------------------------------------------------------------------------
#define SCAN_THREADS 1024
#define SCAN_CHUNK   ((N_NODES + SCAN_THREADS - 1) / SCAN_THREADS)   // 49

__global__ void scan_kernel() {
    __shared__ int wsum[32];
    const int tid  = threadIdx.x;
    const int lane = tid & 31;
    const int wid  = tid >> 5;
    const int lo   = tid * SCAN_CHUNK;
    const int hi   = min(lo + SCAN_CHUNK, N_NODES);

    int v = 0;
    for (int i = lo; i < hi; i++) {
        v += g_cnt[i];
        float d = g_dinv[i];
        g_dinv[i] = (d > 0.f) ? rsqrtf(d) : 0.f;
    }

    int inc = v;
#pragma unroll
    for (int o = 1; o < 32; o <<= 1) {
        int t = __shfl_up_sync(0xffffffffu, inc, o);
        if (lane >= o) inc += t;
    }
    if (lane == 31) wsum[wid] = inc;
    __syncthreads();
    if (wid == 0) {
        int t = wsum[lane];
#pragma unroll
        for (int o = 1; o < 32; o <<= 1) {
            int u = __shfl_up_sync(0xffffffffu, t, o);
            if (lane >= o) t += u;
        }
        wsum[lane] = t;
    }
    __syncthreads();

    int base = ((wid > 0) ? wsum[wid - 1] : 0) + inc - v;
    for (int i = lo; i < hi; i++) {
        g_rowptr[i] = base;
        g_cursor[i] = base;
        base += g_cnt[i];
    }
}

// Stage 3: scatter packed (src, norm) into dst-grouped CSR slots
__global__ void scatter_kernel(const int* __restrict__ ei,
                               const float* __restrict__ ew) {
    int e = blockIdx.x * blockDim.x + threadIdx.x;
    if (e < N_EDGES) {
        int s = ei[e];
        int d = ei[N_EDGES + e];
        float nrm = -g_dinv[s] * ew[e] * g_dinv[d];
        int pos = atomicAdd(&g_cursor[d], 1);
        g_edges[pos] = make_int2(s, __float_as_int(nrm));
    }
}

// ---------------------------------------------------------------------------
// Stage 4/5: gather-side propagation, one warp per dst node (unroll x4).
// ---------------------------------------------------------------------------
__global__ void prop1_csr_kernel(const float* __restrict__ x) {
    int node = (blockIdx.x * blockDim.x + threadIdx.x) >> 5;
    int lane = threadIdx.x & 31;
    if (node >= N_NODES) return;
    int base = g_rowptr[node];
    int cnt  = g_cnt[node];

    float4 acc = make_float4(0.f, 0.f, 0.f, 0.f);
    int j = 0;
    for (; j + 4 <= cnt; j += 4) {
        int2 e0 = g_edges[base + j];
        int2 e1 = g_edges[base + j + 1];
        int2 e2 = g_edges[base + j + 2];
        int2 e3 = g_edges[base + j + 3];
        float4 v0 = ((const float4*)(x + (size_t)e0.x * FDIM))[lane];
        float4 v1 = ((const float4*)(x + (size_t)e1.x * FDIM))[lane];
        float4 v2 = ((const float4*)(x + (size_t)e2.x * FDIM))[lane];
        float4 v3 = ((const float4*)(x + (size_t)e3.x * FDIM))[lane];
        float w0 = __int_as_float(e0.y), w1 = __int_as_float(e1.y);
        float w2 = __int_as_float(e2.y), w3 = __int_as_float(e3.y);
        acc.x += w0*v0.x + w1*v1.x + w2*v2.x + w3*v3.x;
        acc.y += w0*v0.y + w1*v1.y + w2*v2.y + w3*v3.y;
        acc.z += w0*v0.z + w1*v1.z + w2*v2.z + w3*v3.z;
        acc.w += w0*v0.w + w1*v1.w + w2*v2.w + w3*v3.w;
    }
    for (; j < cnt; j++) {
        int2 e0 = g_edges[base + j];
        float w0 = __int_as_float(e0.y);
        float4 v0 = ((const float4*)(x + (size_t)e0.x * FDIM))[lane];
        acc.x += w0*v0.x; acc.y += w0*v0.y; acc.z += w0*v0.z; acc.w += w0*v0.w;
    }
    ((float4*)(g_T1 + (size_t)node * FDIM))[lane] = acc;
}

__global__ void prop2_csr_kernel(const float* __restrict__ x) {
    int node = (blockIdx.x * blockDim.x + threadIdx.x) >> 5;
    int lane = threadIdx.x & 31;
    if (node >= N_NODES) return;
    int base = g_rowptr[node];
    int cnt  = g_cnt[node];

    float4 acc = make_float4(0.f, 0.f, 0.f, 0.f);
    int j = 0;
    for (; j + 4 <= cnt; j += 4) {
        int2 e0 = g_edges[base + j];
        int2 e1 = g_edges[base + j + 1];
        int2 e2 = g_edges[base + j + 2];
        int2 e3 = g_edges[base + j + 3];
        float4 v0 = ((const float4*)(g_T1 + (size_t)e0.x * FDIM))[lane];
        float4 v1 = ((const float4*)(g_T1 + (size_t)e1.x * FDIM))[lane];
        float4 v2 = ((const float4*)(g_T1 + (size_t)e2.x * FDIM))[lane];
        float4 v3 = ((const float4*)(g_T1 + (size_t)e3.x * FDIM))[lane];
        float w0 = __int_as_float(e0.y), w1 = __int_as_float(e1.y);
        float w2 = __int_as_float(e2.y), w3 = __int_as_float(e3.y);
        acc.x += w0*v0.x + w1*v1.x + w2*v2.x + w3*v3.x;
        acc.y += w0*v0.y + w1*v1.y + w2*v2.y + w3*v3.y;
        acc.z += w0*v0.z + w1*v1.z + w2*v2.z + w3*v3.z;
        acc.w += w0*v0.w + w1*v1.w + w2*v2.w + w3*v3.w;
    }
    for (; j < cnt; j++) {
        int2 e0 = g_edges[base + j];
        float w0 = __int_as_float(e0.y);
        float4 v0 = ((const float4*)(g_T1 + (size_t)e0.x * FDIM))[lane];
        acc.x += w0*v0.x; acc.y += w0*v0.y; acc.z += w0*v0.z; acc.w += w0*v0.w;
    }
    float4 xx = ((const float4*)(x + (size_t)node * FDIM))[lane];
    acc.x = 2.f * acc.x - xx.x;
    acc.y = 2.f * acc.y - xx.y;
    acc.z = 2.f * acc.z - xx.z;
    acc.w = 2.f * acc.w - xx.w;
    ((float4*)(g_T2 + (size_t)node * FDIM))[lane] = acc;
}

// ---------------------------------------------------------------------------
// Stage 6: fused GEMM (tensor cores, 3xTF32, pre-split B) + gate + projection
//   BM=64, BN=256, BK=16, 8 warps (2M x 4N)
// ---------------------------------------------------------------------------
#define BM   64
#define BKT  16
#define NKB  24
#define A_STRIDE 17
#define B_STRIDE 260
#define A_FLOATS (BM * A_STRIDE)                     // 1088
#define B_TILE   (BKT * B_STRIDE)                    // 4160
#define STG_FLOATS (A_FLOATS + 2 * B_TILE)           // 1088 + 8320 = 9408
#define ZB_STRIDE 132
#define ZBUF_OFF  0
#define HBUF_OFF  (BM * ZB_STRIDE)                   // 8448
#define WLT_OFF   (2 * BM * ZB_STRIDE)               // 16896
#define BZS_OFF   (WLT_OFF + TDIM * HDIM)            // 18176
#define BHS_OFF   (BZS_OFF + HDIM)                   // 18304
#define SMEM_FLOATS_TOTAL (2 * STG_FLOATS)           // 18816 -> 75264 B

extern __shared__ float smem[];

__device__ __forceinline__ void cp_async16(uint32_t saddr, const void* g, int bytes) {
    asm volatile("cp.async.cg.shared.global [%0], [%1], 16, %2;"
                 :: "r"(saddr), "l"(g), "r"(bytes) : "memory");
}
__device__ __forceinline__ void cp_async4(uint32_t saddr, const void* g, int bytes) {
    asm volatile("cp.async.ca.shared.global [%0], [%1], 4, %2;"
                 :: "r"(saddr), "l"(g), "r"(bytes) : "memory");
}

__device__ __forceinline__ void mma_tf32(float* c, const uint32_t* a, const uint32_t* b) {
    asm volatile(
        "mma.sync.aligned.m16n8k8.row.col.f32.tf32.tf32.f32 "
        "{%0,%1,%2,%3}, {%4,%5,%6,%7}, {%8,%9}, {%0,%1,%2,%3};"
        : "+f"(c[0]), "+f"(c[1]), "+f"(c[2]), "+f"(c[3])
        : "r"(a[0]), "r"(a[1]), "r"(a[2]), "r"(a[3]),
          "r"(b[0]), "r"(b[1]));
}

__global__ __launch_bounds__(256, 2) void fused_kernel(
    const float* __restrict__ x,
    const float* __restrict__ bz0, const float* __restrict__ bz1,
    const float* __restrict__ bh0, const float* __restrict__ bh1,
    const float* __restrict__ Wlin, const float* __restrict__ blin,
    float* __restrict__ out)
{
    const int tid  = threadIdx.x;
    const int lane = tid & 31;
    const int wid  = tid >> 5;
    const int wm   = wid & 1;
    const int wn   = wid >> 1;
    const int mwb  = wm * 32;
    const int nwb  = wn * 64;
    const int m0   = blockIdx.x * BM;

    const uint32_t smem_u32 = (uint32_t)__cvta_generic_to_shared(smem);

    float c[2][8][4];
#pragma unroll
    for (int mi = 0; mi < 2; mi++)
#pragma unroll
        for (int ni = 0; ni < 8; ni++)
#pragma unroll
            for (int q = 0; q < 4; q++) c[mi][ni][q] = 0.f;

    auto load_stage = [&](int kb, int s) {
        const int col = kb * BKT;
        const float* Asrc;
        int c0;
        if (col < 128)      { Asrc = x;    c0 = col; }
        else if (col < 256) { Asrc = g_T1; c0 = col - 128; }
        else                { Asrc = g_T2; c0 = col - 256; }

        uint32_t sa  = smem_u32 + (uint32_t)(s * STG_FLOATS) * 4u;
        uint32_t sbb = sa + (uint32_t)A_FLOATS * 4u;
        uint32_t sbd = sbb + (uint32_t)B_TILE * 4u;

        // A tile: 64 rows x 16 k = 1024 floats -> 4 per thread
#pragma unroll
        for (int j = 0; j < 4; j++) {
            int idx = tid + j * 256;
            int m = idx >> 4;
            int k = idx & 15;
            int node  = m0 + m;
            int bytes = (node < N_NODES) ? 4 : 0;
            int nd    = (node < N_NODES) ? node : 0;
            cp_async4(sa + (uint32_t)(m * A_STRIDE + k) * 4u,
                      Asrc + (size_t)nd * FDIM + c0 + k, bytes);
        }
        // B tiles (pre-split big + delta): 16 rows x 256 = 1024 float4 each
#pragma unroll
        for (int j = 0; j < 4; j++) {
            int idx  = tid + j * 256;
            int jr   = idx >> 6;
            int col4 = (idx & 63) * 4;
            size_t goff = (size_t)(col + jr) * 256 + col4;
            cp_async16(sbb + (uint32_t)(jr * B_STRIDE + col4) * 4u, g_Bb + goff, 16);
            cp_async16(sbd + (uint32_t)(jr * B_STRIDE + col4) * 4u, g_Bd + goff, 16);
        }
        asm volatile("cp.async.commit_group;" ::: "memory");
    };

    load_stage(0, 0);

    const int ar = lane >> 2;
    const int ac = lane & 3;

    for (int kb = 0; kb < NKB; kb++) {
        int s = kb & 1;
        if (kb + 1 < NKB) {
            load_stage(kb + 1, s ^ 1);
            asm volatile("cp.async.wait_group 1;" ::: "memory");
        } else {
            asm volatile("cp.async.wait_group 0;" ::: "memory");
        }
        __syncthreads();

        const float*    A  = smem + s * STG_FLOATS;
        const uint32_t* Bb = (const uint32_t*)(A + A_FLOATS);
        const uint32_t* Bd = Bb + B_TILE;

#pragma unroll
        for (int k8 = 0; k8 < 2; k8++) {
            const int kk = k8 * 8;

            uint32_t ab[2][4], ad[2][4];
#pragma unroll
            for (int mi = 0; mi < 2; mi++) {
                int r0 = mwb + mi * 16 + ar;
                float v0 = A[r0 * A_STRIDE + kk + ac];
                float v1 = A[(r0 + 8) * A_STRIDE + kk + ac];
                float v2 = A[r0 * A_STRIDE + kk + ac + 4];
                float v3 = A[(r0 + 8) * A_STRIDE + kk + ac + 4];
                ab[mi][0] = f2tf32(v0); ad[mi][0] = f2tf32(v0 - __uint_as_float(ab[mi][0]));
                ab[mi][1] = f2tf32(v1); ad[mi][1] = f2tf32(v1 - __uint_as_float(ab[mi][1]));
                ab[mi][2] = f2tf32(v2); ad[mi][2] = f2tf32(v2 - __uint_as_float(ab[mi][2]));
                ab[mi][3] = f2tf32(v3); ad[mi][3] = f2tf32(v3 - __uint_as_float(ab[mi][3]));
            }

            uint32_t bb[8][2], bd[8][2];
#pragma unroll
            for (int ni = 0; ni < 8; ni++) {
                int br = kk + ac;
                int bc = nwb + ni * 8 + ar;
                bb[ni][0] = Bb[br * B_STRIDE + bc];
                bb[ni][1] = Bb[(br + 4) * B_STRIDE + bc];
                bd[ni][0] = Bd[br * B_STRIDE + bc];
                bd[ni][1] = Bd[(br + 4) * B_STRIDE + bc];
            }

#pragma unroll
            for (int mi = 0; mi < 2; mi++) {
#pragma unroll
                for (int ni = 0; ni < 8; ni++) {
                    mma_tf32(c[mi][ni], ab[mi], bb[ni]);
                    mma_tf32(c[mi][ni], ab[mi], bd[ni]);
                    mma_tf32(c[mi][ni], ad[mi], bb[ni]);
                }
            }
        }
        __syncthreads();
    }

    // ---- write accumulators to zbuf/hbuf ----
    float* zbuf = smem + ZBUF_OFF;
    float* hbuf = smem + HBUF_OFF;
#pragma unroll
    for (int mi = 0; mi < 2; mi++) {
#pragma unroll
        for (int ni = 0; ni < 8; ni++) {
            int m = mwb + mi * 16 + ar;
            int n = nwb + ni * 8 + ac * 2;
            float* buf = (n < 128) ? (zbuf + n) : (hbuf + n - 128);
            buf[m * ZB_STRIDE]           = c[mi][ni][0];
            buf[m * ZB_STRIDE + 1]       = c[mi][ni][1];
            buf[(m + 8) * ZB_STRIDE]     = c[mi][ni][2];
            buf[(m + 8) * ZB_STRIDE + 1] = c[mi][ni][3];
        }
    }

    float* WlinT = smem + WLT_OFF;
    float* bzs   = smem + BZS_OFF;
    float* bhs   = smem + BHS_OFF;
    if (tid < 128) {
        bzs[tid] = bz0[tid] + bz1[tid];
        bhs[tid] = bh0[tid] + bh1[tid];
    }
    for (int idx = tid; idx < TDIM * HDIM; idx += 256) {
        int t = idx % TDIM;
        int h = idx / TDIM;
        WlinT[t * HDIM + h] = Wlin[h * TDIM + t];
    }
    __syncthreads();

    // ---- gate ----
    for (int idx = tid; idx < BM * HDIM; idx += 256) {
        int m = idx >> 7;
        int h = idx & 127;
        float z  = zbuf[m * ZB_STRIDE + h] + bzs[h];
        float hp = hbuf[m * ZB_STRIDE + h] + bhs[h];
        float sig = 1.f / (1.f + __expf(-z));
        zbuf[m * ZB_STRIDE + h] = (1.f - sig) * tanhf(hp);
    }
    __syncthreads();

    // ---- output projection ----
    if (tid < 2 * BM) {
        int m = tid >> 1;
        int g = tid & 1;
        int node = m0 + m;
        if (node < N_NODES) {
            float acc[5];
#pragma unroll
            for (int j = 0; j < 5; j++) acc[j] = blin[g * 5 + j];
            const float* hrow = zbuf + m * ZB_STRIDE;
#pragma unroll 8
            for (int h = 0; h < HDIM; h++) {
                float v = hrow[h];
#pragma unroll
                for (int j = 0; j < 5; j++)
                    acc[j] += v * WlinT[(g * 5 + j) * HDIM + h];
            }
#pragma unroll
            for (int j = 0; j < 5; j++)
                out[(size_t)node * TDIM + g * 5 + j] = acc[j];
        }
    }
}

// ---------------------------------------------------------------------------
// Launch
// ---------------------------------------------------------------------------
extern "C" void kernel_launch(void* const* d_in, const int* in_sizes, int n_in,
                              void* d_out, int out_size) {
    const float* x    = (const float*)d_in[0];
    const int*   ei   = (const int*)d_in[1];      // int32 (JAX x64 disabled)
    const float* ew   = (const float*)d_in[2];
    const float* Wxz  = (const float*)d_in[3];
    const float* bxz  = (const float*)d_in[4];
    const float* bhz  = (const float*)d_in[6];
    const float* Wxh  = (const float*)d_in[11];
    const float* bxh  = (const float*)d_in[12];
    const float* bhh  = (const float*)d_in[14];
    const float* Wlin = (const float*)d_in[15];
    const float* blin = (const float*)d_in[16];
    float*       out  = (float*)d_out;

    const int smem_bytes = SMEM_FLOATS_TOTAL * sizeof(float);   // 75264
    cudaFuncSetAttribute(fused_kernel,
                         cudaFuncAttributeMaxDynamicSharedMemorySize, smem_bytes);

    // Preamble
    split_kernel<<<(384 * 256 + 255) / 256, 256>>>(Wxz, Wxh);
    init_kernel<<<(N_NODES + 255) / 256, 256>>>();
    deg_kernel<<<(N_EDGES + 255) / 256, 256>>>(ei, ew);
    scan_kernel<<<1, SCAN_THREADS>>>();
    scatter_kernel<<<(N_EDGES + 255) / 256, 256>>>(ei, ew);

    // Gather-side propagation
    const int PROP_BLOCKS = (N_NODES * 32 + 255) / 256;
    prop1_csr_kernel<<<PROP_BLOCKS, 256>>>(x);
    prop2_csr_kernel<<<PROP_BLOCKS, 256>>>(x);

    fused_kernel<<<(N_NODES + BM - 1) / BM, 256, smem_bytes>>>(
        x, bxz, bhz, bxh, bhh, Wlin, blin, out);
}

// round 12
// speedup vs baseline: 1.6221x; 1.3289x over previous
#include <cuda_runtime.h>
#include <cstdint>

#define N_NODES 50000
#define N_EDGES 800000
#define FDIM    128
#define HDIM    128
#define TDIM    10
#define NB      ((N_NODES + 255) / 256)    // 196 scan blocks

// Scratch (device globals) — only ever referenced from DEVICE code.
__device__ __align__(16) float g_dinv[N_NODES];
__device__ int  g_cnt[N_NODES];
__device__ int  g_rowptr[N_NODES];
__device__ int  g_cursor[N_NODES];
__device__ int  g_blocksum[NB];
__device__ int  g_blockoff[NB];
__device__ __align__(16) int2  g_edges[N_EDGES];
__device__ __align__(16) float g_T1[N_NODES * FDIM];
__device__ __align__(16) float g_T2[N_NODES * FDIM];
// Pre-split B operand (tf32 big + delta), concatenated layout [384][256] = [k][z|h]
__device__ __align__(16) uint32_t g_Bb[384 * 256];
__device__ __align__(16) uint32_t g_Bd[384 * 256];

__device__ __forceinline__ uint32_t f2tf32(float v) {
    uint32_t o;
    asm("cvt.rna.tf32.f32 %0, %1;" : "=r"(o) : "f"(v));
    return o;
}

// ---------------------------------------------------------------------------
// Stage 0a: pre-split weights into tf32 big/delta
// ---------------------------------------------------------------------------
__global__ void split_kernel(const float* __restrict__ Wz,
                             const float* __restrict__ Wh) {
    int idx = blockIdx.x * blockDim.x + threadIdx.x;
    if (idx < 384 * 256) {
        int k = idx >> 8;
        int c = idx & 255;
        float v = (c < 128) ? Wz[k * 128 + c] : Wh[k * 128 + (c - 128)];
        uint32_t big = f2tf32(v);
        g_Bb[idx] = big;
        g_Bd[idx] = f2tf32(v - __uint_as_float(big));
    }
}

// Stage 0b: zero degree / per-dst count
__global__ void init_kernel() {
    int n = blockIdx.x * blockDim.x + threadIdx.x;
    if (n < N_NODES) { g_dinv[n] = 0.f; g_cnt[n] = 0; }
}

// Stage 1: deg[src] += w ; cnt[dst] += 1        (edge_index is int32)
__global__ void deg_kernel(const int* __restrict__ ei,
                           const float* __restrict__ ew) {
    int e = blockIdx.x * blockDim.x + threadIdx.x;
    if (e < N_EDGES) {
        atomicAdd(&g_dinv[ei[e]], ew[e]);
        atomicAdd(&g_cnt[ei[N_EDGES + e]], 1);
    }
}

// ---------------------------------------------------------------------------
// Stage 2: grid-wide 3-phase exclusive scan (replaces 114us single-block scan)
// ---------------------------------------------------------------------------
// Phase 1: dinv transform + per-block sums
__global__ void blocksum_kernel() {
    int i = blockIdx.x * 256 + threadIdx.x;
    int v = 0;
    if (i < N_NODES) {
        v = g_cnt[i];
        float d = g_dinv[i];
        g_dinv[i] = (d > 0.f) ? rsqrtf(d) : 0.f;
    }
    __shared__ int ws[8];
    int lane = threadIdx.x & 31, wid = threadIdx.x >> 5;
#pragma unroll
    for (int o = 16; o > 0; o >>= 1) v += __shfl_down_sync(0xffffffffu, v, o);
    if (lane == 0) ws[wid] = v;
    __syncthreads();
    if (threadIdx.x == 0) {
        int s = 0;
#pragma unroll
        for (int w = 0; w < 8; w++) s += ws[w];
        g_blocksum[blockIdx.x] = s;
    }
}

// Phase 2: exclusive scan of NB block sums (1 block, 256 threads)
__global__ void blockscan_kernel() {
    __shared__ int ws[8];
    int tid = threadIdx.x, lane = tid & 31, wid = tid >> 5;
    int v = (tid < NB) ? g_blocksum[tid] : 0;
    int inc = v;
#pragma unroll
    for (int o = 1; o < 32; o <<= 1) {
        int t = __shfl_up_sync(0xffffffffu, inc, o);
        if (lane >= o) inc += t;
    }
    if (lane == 31) ws[wid] = inc;
    __syncthreads();
    if (wid == 0 && lane < 8) {
        int t = ws[lane];
#pragma unroll
        for (int o = 1; o < 8; o <<= 1) {
            int u = __shfl_up_sync(0xffu, t, o);
            if (lane >= o) t += u;
        }
        ws[lane] = t;
    }
    __syncthreads();
    int excl = inc - v + ((wid > 0) ? ws[wid - 1] : 0);
    if (tid < NB) g_blockoff[tid] = excl;
}

// Phase 3: block-internal exclusive scan + block offset -> rowptr/cursor
__global__ void rowptr_kernel() {
    int i = blockIdx.x * 256 + threadIdx.x;
    int v = (i < N_NODES) ? g_cnt[i] : 0;
    __shared__ int ws[8];
    int lane = threadIdx.x & 31, wid = threadIdx.x >> 5;
    int inc = v;
#pragma unroll
    for (int o = 1; o < 32; o <<= 1) {
        int t = __shfl_up_sync(0xffffffffu, inc, o);
        if (lane >= o) inc += t;
    }
    if (lane == 31) ws[wid] = inc;
    __syncthreads();
    if (wid == 0 && lane < 8) {
        int t = ws[lane];
#pragma unroll
        for (int o = 1; o < 8; o <<= 1) {
            int u = __shfl_up_sync(0xffu, t, o);
            if (lane >= o) t += u;
        }
        ws[lane] = t;
    }
    __syncthreads();
    int excl = inc - v + ((wid > 0) ? ws[wid - 1] : 0) + g_blockoff[blockIdx.x];
    if (i < N_NODES) { g_rowptr[i] = excl; g_cursor[i] = excl; }
}

// Stage 3: scatter packed (src, norm) into dst-grouped CSR slots
__global__ void scatter_kernel(const int* __restrict__ ei,
                               const float* __restrict__ ew) {
    int e = blockIdx.x * blockDim.x + threadIdx.x;
    if (e < N_EDGES) {
        int s = ei[e];
        int d = ei[N_EDGES + e];
        float nrm = -g_dinv[s] * ew[e] * g_dinv[d];
        int pos = atomicAdd(&g_cursor[d], 1);
        g_edges[pos] = make_int2(s, __float_as_int(nrm));
    }
}

// ---------------------------------------------------------------------------
// Stage 4/5: gather-side propagation, one warp per dst node (unroll x4).
// ---------------------------------------------------------------------------
__global__ void prop1_csr_kernel(const float* __restrict__ x) {
    int node = (blockIdx.x * blockDim.x + threadIdx.x) >> 5;
    int lane = threadIdx.x & 31;
    if (node >= N_NODES) return;
    int base = g_rowptr[node];
    int cnt  = g_cnt[node];

    float4 acc = make_float4(0.f, 0.f, 0.f, 0.f);
    int j = 0;
    for (; j + 4 <= cnt; j += 4) {
        int2 e0 = g_edges[base + j];
        int2 e1 = g_edges[base + j + 1];
        int2 e2 = g_edges[base + j + 2];
        int2 e3 = g_edges[base + j + 3];
        float4 v0 = ((const float4*)(x + (size_t)e0.x * FDIM))[lane];
        float4 v1 = ((const float4*)(x + (size_t)e1.x * FDIM))[lane];
        float4 v2 = ((const float4*)(x + (size_t)e2.x * FDIM))[lane];
        float4 v3 = ((const float4*)(x + (size_t)e3.x * FDIM))[lane];
        float w0 = __int_as_float(e0.y), w1 = __int_as_float(e1.y);
        float w2 = __int_as_float(e2.y), w3 = __int_as_float(e3.y);
        acc.x += w0*v0.x + w1*v1.x + w2*v2.x + w3*v3.x;
        acc.y += w0*v0.y + w1*v1.y + w2*v2.y + w3*v3.y;
        acc.z += w0*v0.z + w1*v1.z + w2*v2.z + w3*v3.z;
        acc.w += w0*v0.w + w1*v1.w + w2*v2.w + w3*v3.w;
    }
    for (; j < cnt; j++) {
        int2 e0 = g_edges[base + j];
        float w0 = __int_as_float(e0.y);
        float4 v0 = ((const float4*)(x + (size_t)e0.x * FDIM))[lane];
        acc.x += w0*v0.x; acc.y += w0*v0.y; acc.z += w0*v0.z; acc.w += w0*v0.w;
    }
    ((float4*)(g_T1 + (size_t)node * FDIM))[lane] = acc;
}

__global__ void prop2_csr_kernel(const float* __restrict__ x) {
    int node = (blockIdx.x * blockDim.x + threadIdx.x) >> 5;
    int lane = threadIdx.x & 31;
    if (node >= N_NODES) return;
    int base = g_rowptr[node];
    int cnt  = g_cnt[node];

    float4 acc = make_float4(0.f, 0.f, 0.f, 0.f);
    int j = 0;
    for (; j + 4 <= cnt; j += 4) {
        int2 e0 = g_edges[base + j];
        int2 e1 = g_edges[base + j + 1];
        int2 e2 = g_edges[base + j + 2];
        int2 e3 = g_edges[base + j + 3];
        float4 v0 = ((const float4*)(g_T1 + (size_t)e0.x * FDIM))[lane];
        float4 v1 = ((const float4*)(g_T1 + (size_t)e1.x * FDIM))[lane];
        float4 v2 = ((const float4*)(g_T1 + (size_t)e2.x * FDIM))[lane];
        float4 v3 = ((const float4*)(g_T1 + (size_t)e3.x * FDIM))[lane];
        float w0 = __int_as_float(e0.y), w1 = __int_as_float(e1.y);
        float w2 = __int_as_float(e2.y), w3 = __int_as_float(e3.y);
        acc.x += w0*v0.x + w1*v1.x + w2*v2.x + w3*v3.x;
        acc.y += w0*v0.y + w1*v1.y + w2*v2.y + w3*v3.y;
        acc.z += w0*v0.z + w1*v1.z + w2*v2.z + w3*v3.z;
        acc.w += w0*v0.w + w1*v1.w + w2*v2.w + w3*v3.w;
    }
    for (; j < cnt; j++) {
        int2 e0 = g_edges[base + j];
        float w0 = __int_as_float(e0.y);
        float4 v0 = ((const float4*)(g_T1 + (size_t)e0.x * FDIM))[lane];
        acc.x += w0*v0.x; acc.y += w0*v0.y; acc.z += w0*v0.z; acc.w += w0*v0.w;
    }
    float4 xx = ((const float4*)(x + (size_t)node * FDIM))[lane];
    acc.x = 2.f * acc.x - xx.x;
    acc.y = 2.f * acc.y - xx.y;
    acc.z = 2.f * acc.z - xx.z;
    acc.w = 2.f * acc.w - xx.w;
    ((float4*)(g_T2 + (size_t)node * FDIM))[lane] = acc;
}

// ---------------------------------------------------------------------------
// Stage 6: fused GEMM (tensor cores, 3xTF32, pre-split B) + gate + projection
// ---------------------------------------------------------------------------
#define BM   64
#define BKT  16
#define NKB  24
#define A_STRIDE 17
#define B_STRIDE 260
#define A_FLOATS (BM * A_STRIDE)
#define B_TILE   (BKT * B_STRIDE)
#define STG_FLOATS (A_FLOATS + 2 * B_TILE)           // 9408
#define ZB_STRIDE 132
#define ZBUF_OFF  0
#define HBUF_OFF  (BM * ZB_STRIDE)
#define WLT_OFF   (2 * BM * ZB_STRIDE)
#define BZS_OFF   (WLT_OFF + TDIM * HDIM)
#define BHS_OFF   (BZS_OFF + HDIM)
#define SMEM_FLOATS_TOTAL (2 * STG_FLOATS)           // 18816 -> 75264 B

extern __shared__ float smem[];

__device__ __forceinline__ void cp_async16(uint32_t saddr, const void* g, int bytes) {
    asm volatile("cp.async.cg.shared.global [%0], [%1], 16, %2;"
                 :: "r"(saddr), "l"(g), "r"(bytes) : "memory");
}
__device__ __forceinline__ void cp_async4(uint32_t saddr, const void* g, int bytes) {
    asm volatile("cp.async.ca.shared.global [%0], [%1], 4, %2;"
                 :: "r"(saddr), "l"(g), "r"(bytes) : "memory");
}

__device__ __forceinline__ void mma_tf32(float* c, const uint32_t* a, const uint32_t* b) {
    asm volatile(
        "mma.sync.aligned.m16n8k8.row.col.f32.tf32.tf32.f32 "
        "{%0,%1,%2,%3}, {%4,%5,%6,%7}, {%8,%9}, {%0,%1,%2,%3};"
        : "+f"(c[0]), "+f"(c[1]), "+f"(c[2]), "+f"(c[3])
        : "r"(a[0]), "r"(a[1]), "r"(a[2]), "r"(a[3]),
          "r"(b[0]), "r"(b[1]));
}

__global__ __launch_bounds__(256, 2) void fused_kernel(
    const float* __restrict__ x,
    const float* __restrict__ bz0, const float* __restrict__ bz1,
    const float* __restrict__ bh0, const float* __restrict__ bh1,
    const float* __restrict__ Wlin, const float* __restrict__ blin,
    float* __restrict__ out)
{
    const int tid  = threadIdx.x;
    const int lane = tid & 31;
    const int wid  = tid >> 5;
    const int wm   = wid & 1;
    const int wn   = wid >> 1;
    const int mwb  = wm * 32;
    const int nwb  = wn * 64;
    const int m0   = blockIdx.x * BM;

    const uint32_t smem_u32 = (uint32_t)__cvta_generic_to_shared(smem);

    float c[2][8][4];
#pragma unroll
    for (int mi = 0; mi < 2; mi++)
#pragma unroll
        for (int ni = 0; ni < 8; ni++)
#pragma unroll
            for (int q = 0; q < 4; q++) c[mi][ni][q] = 0.f;

    auto load_stage = [&](int kb, int s) {
        const int col = kb * BKT;
        const float* Asrc;
        int c0;
        if (col < 128)      { Asrc = x;    c0 = col; }
        else if (col < 256) { Asrc = g_T1; c0 = col - 128; }
        else                { Asrc = g_T2; c0 = col - 256; }

        uint32_t sa  = smem_u32 + (uint32_t)(s * STG_FLOATS) * 4u;
        uint32_t sbb = sa + (uint32_t)A_FLOATS * 4u;
        uint32_t sbd = sbb + (uint32_t)B_TILE * 4u;

#pragma unroll
        for (int j = 0; j < 4; j++) {
            int idx = tid + j * 256;
            int m = idx >> 4;
            int k = idx & 15;
            int node  = m0 + m;
            int bytes = (node < N_NODES) ? 4 : 0;
            int nd    = (node < N_NODES) ? node : 0;
            cp_async4(sa + (uint32_t)(m * A_STRIDE + k) * 4u,
                      Asrc + (size_t)nd * FDIM + c0 + k, bytes);
        }
#pragma unroll
        for (int j = 0; j < 4; j++) {
            int idx  = tid + j * 256;
            int jr   = idx >> 6;
            int col4 = (idx & 63) * 4;
            size_t goff = (size_t)(col + jr) * 256 + col4;
            cp_async16(sbb + (uint32_t)(jr * B_STRIDE + col4) * 4u, g_Bb + goff, 16);
            cp_async16(sbd + (uint32_t)(jr * B_STRIDE + col4) * 4u, g_Bd + goff, 16);
        }
        asm volatile("cp.async.commit_group;" ::: "memory");
    };

    load_stage(0, 0);

    const int ar = lane >> 2;
    const int ac = lane & 3;

    for (int kb = 0; kb < NKB; kb++) {
        int s = kb & 1;
        if (kb + 1 < NKB) {
            load_stage(kb + 1, s ^ 1);
            asm volatile("cp.async.wait_group 1;" ::: "memory");
        } else {
            asm volatile("cp.async.wait_group 0;" ::: "memory");
        }
        __syncthreads();

        const float*    A  = smem + s * STG_FLOATS;
        const uint32_t* Bb = (const uint32_t*)(A + A_FLOATS);
        const uint32_t* Bd = Bb + B_TILE;

#pragma unroll
        for (int k8 = 0; k8 < 2; k8++) {
            const int kk = k8 * 8;

            uint32_t ab[2][4], ad[2][4];
#pragma unroll
            for (int mi = 0; mi < 2; mi++) {
                int r0 = mwb + mi * 16 + ar;
                float v0 = A[r0 * A_STRIDE + kk + ac];
                float v1 = A[(r0 + 8) * A_STRIDE + kk + ac];
                float v2 = A[r0 * A_STRIDE + kk + ac + 4];
                float v3 = A[(r0 + 8) * A_STRIDE + kk + ac + 4];
                ab[mi][0] = f2tf32(v0); ad[mi][0] = f2tf32(v0 - __uint_as_float(ab[mi][0]));
                ab[mi][1] = f2tf32(v1); ad[mi][1] = f2tf32(v1 - __uint_as_float(ab[mi][1]));
                ab[mi][2] = f2tf32(v2); ad[mi][2] = f2tf32(v2 - __uint_as_float(ab[mi][2]));
                ab[mi][3] = f2tf32(v3); ad[mi][3] = f2tf32(v3 - __uint_as_float(ab[mi][3]));
            }

            uint32_t bb[8][2], bd[8][2];
#pragma unroll
            for (int ni = 0; ni < 8; ni++) {
                int br = kk + ac;
                int bc = nwb + ni * 8 + ar;
                bb[ni][0] = Bb[br * B_STRIDE + bc];
                bb[ni][1] = Bb[(br + 4) * B_STRIDE + bc];
                bd[ni][0] = Bd[br * B_STRIDE + bc];
                bd[ni][1] = Bd[(br + 4) * B_STRIDE + bc];
            }

#pragma unroll
            for (int mi = 0; mi < 2; mi++) {
#pragma unroll
                for (int ni = 0; ni < 8; ni++) {
                    mma_tf32(c[mi][ni], ab[mi], bb[ni]);
                    mma_tf32(c[mi][ni], ab[mi], bd[ni]);
                    mma_tf32(c[mi][ni], ad[mi], bb[ni]);
                }
            }
        }
        __syncthreads();
    }

    // ---- write accumulators to zbuf/hbuf ----
    float* zbuf = smem + ZBUF_OFF;
    float* hbuf = smem + HBUF_OFF;
#pragma unroll
    for (int mi = 0; mi < 2; mi++) {
#pragma unroll
        for (int ni = 0; ni < 8; ni++) {
            int m = mwb + mi * 16 + ar;
            int n = nwb + ni * 8 + ac * 2;
            float* buf = (n < 128) ? (zbuf + n) : (hbuf + n - 128);
            buf[m * ZB_STRIDE]           = c[mi][ni][0];
            buf[m * ZB_STRIDE + 1]       = c[mi][ni][1];
            buf[(m + 8) * ZB_STRIDE]     = c[mi][ni][2];
            buf[(m + 8) * ZB_STRIDE + 1] = c[mi][ni][3];
        }
    }

    float* WlinT = smem + WLT_OFF;
    float* bzs   = smem + BZS_OFF;
    float* bhs   = smem + BHS_OFF;
    if (tid < 128) {
        bzs[tid] = bz0[tid] + bz1[tid];
        bhs[tid] = bh0[tid] + bh1[tid];
    }
    for (int idx = tid; idx < TDIM * HDIM; idx += 256) {
        int t = idx % TDIM;
        int h = idx / TDIM;
        WlinT[t * HDIM + h] = Wlin[h * TDIM + t];
    }
    __syncthreads();

    // ---- gate ----
    for (int idx = tid; idx < BM * HDIM; idx += 256) {
        int m = idx >> 7;
        int h = idx & 127;
        float z  = zbuf[m * ZB_STRIDE + h] + bzs[h];
        float hp = hbuf[m * ZB_STRIDE + h] + bhs[h];
        float sig = 1.f / (1.f + __expf(-z));
        zbuf[m * ZB_STRIDE + h] = (1.f - sig) * tanhf(hp);
    }
    __syncthreads();

    // ---- output projection ----
    if (tid < 2 * BM) {
        int m = tid >> 1;
        int g = tid & 1;
        int node = m0 + m;
        if (node < N_NODES) {
            float acc[5];
#pragma unroll
            for (int j = 0; j < 5; j++) acc[j] = blin[g * 5 + j];
            const float* hrow = zbuf + m * ZB_STRIDE;
#pragma unroll 8
            for (int h = 0; h < HDIM; h++) {
                float v = hrow[h];
#pragma unroll
                for (int j = 0; j < 5; j++)
                    acc[j] += v * WlinT[(g * 5 + j) * HDIM + h];
            }
#pragma unroll
            for (int j = 0; j < 5; j++)
                out[(size_t)node * TDIM + g * 5 + j] = acc[j];
        }
    }
}

// ---------------------------------------------------------------------------
// Launch
// ---------------------------------------------------------------------------
extern "C" void kernel_launch(void* const* d_in, const int* in_sizes, int n_in,
                              void* d_out, int out_size) {
    const float* x    = (const float*)d_in[0];
    const int*   ei   = (const int*)d_in[1];      // int32 (JAX x64 disabled)
    const float* ew   = (const float*)d_in[2];
    const float* Wxz  = (const float*)d_in[3];
    const float* bxz  = (const float*)d_in[4];
    const float* bhz  = (const float*)d_in[6];
    const float* Wxh  = (const float*)d_in[11];
    const float* bxh  = (const float*)d_in[12];
    const float* bhh  = (const float*)d_in[14];
    const float* Wlin = (const float*)d_in[15];
    const float* blin = (const float*)d_in[16];
    float*       out  = (float*)d_out;

    const int smem_bytes = SMEM_FLOATS_TOTAL * sizeof(float);   // 75264
    cudaFuncSetAttribute(fused_kernel,
                         cudaFuncAttributeMaxDynamicSharedMemorySize, smem_bytes);

    // Preamble
    split_kernel<<<(384 * 256 + 255) / 256, 256>>>(Wxz, Wxh);
    init_kernel<<<(N_NODES + 255) / 256, 256>>>();
    deg_kernel<<<(N_EDGES + 255) / 256, 256>>>(ei, ew);
    blocksum_kernel<<<NB, 256>>>();
    blockscan_kernel<<<1, 256>>>();
    rowptr_kernel<<<NB, 256>>>();
    scatter_kernel<<<(N_EDGES + 255) / 256, 256>>>(ei, ew);

    // Gather-side propagation
    const int PROP_BLOCKS = (N_NODES * 32 + 255) / 256;
    prop1_csr_kernel<<<PROP_BLOCKS, 256>>>(x);
    prop2_csr_kernel<<<PROP_BLOCKS, 256>>>(x);

    fused_kernel<<<(N_NODES + BM - 1) / BM, 256, smem_bytes>>>(
        x, bxz, bhz, bxh, bhh, Wlin, blin, out);
}

// round 13
// speedup vs baseline: 1.6971x; 1.0462x over previous
#include <cuda_runtime.h>
#include <cuda_fp16.h>
#include <cstdint>

#define N_NODES 50000
#define N_EDGES 800000
#define FDIM    128
#define HDIM    128
#define TDIM    10
#define NB      ((N_NODES + 255) / 256)    // 196 scan blocks

// Scratch (device globals) — only ever referenced from DEVICE code.
__device__ __align__(16) float g_dinv[N_NODES];
__device__ int  g_cnt[N_NODES];
__device__ int  g_rowptr[N_NODES];
__device__ int  g_cursor[N_NODES];
__device__ int  g_blocksum[NB];
__device__ int  g_blockoff[NB];
__device__ __align__(16) int2   g_edges[N_EDGES];
// fp16 A-side data path (exactly representable in tf32 -> no A delta needed)
__device__ __align__(16) __half g_x16[N_NODES * FDIM];
__device__ __align__(16) __half g_T1h[N_NODES * FDIM];
__device__ __align__(16) __half g_T2h[N_NODES * FDIM];   // holds P = L_hat @ T1
// Pre-split B (tf32 big+delta), weight-folded: rows<128: W0-W2; 128-255: W1; >=256: 2*W2
__device__ __align__(16) uint32_t g_Bb[384 * 256];
__device__ __align__(16) uint32_t g_Bd[384 * 256];

__device__ __forceinline__ uint32_t f2tf32(float v) {
    uint32_t o;
    asm("cvt.rna.tf32.f32 %0, %1;" : "=r"(o) : "f"(v));
    return o;
}

// ---------------------------------------------------------------------------
// Stage 0a: weight fold + tf32 split + init (one launch, 98304 threads)
// ---------------------------------------------------------------------------
__global__ void split_kernel(const float* __restrict__ Wz,
                             const float* __restrict__ Wh) {
    int idx = blockIdx.x * blockDim.x + threadIdx.x;
    if (idx < N_NODES) { g_dinv[idx] = 0.f; g_cnt[idx] = 0; }
    if (idx < 384 * 256) {
        int k = idx >> 8;
        int c = idx & 255;
        const float* W = (c < 128) ? Wz : Wh;
        int cc = c & 127;
        float v;
        if (k < 128)      v = W[k * 128 + cc] - W[(k + 256) * 128 + cc];  // W0 - W2
        else if (k < 256) v = W[k * 128 + cc];                            // W1
        else              v = 2.f * W[k * 128 + cc];                      // 2*W2
        uint32_t big = f2tf32(v);
        g_Bb[idx] = big;
        g_Bd[idx] = f2tf32(v - __uint_as_float(big));
    }
}

// Stage 0b: x -> fp16 copy
__global__ void cvtx_kernel(const float* __restrict__ x) {
    int i = blockIdx.x * blockDim.x + threadIdx.x;
    if (i < N_NODES * FDIM / 4) {
        float4 v = ((const float4*)x)[i];
        __half2 lo = __floats2half2_rn(v.x, v.y);
        __half2 hi = __floats2half2_rn(v.z, v.w);
        uint2 o;
        o.x = *reinterpret_cast<uint32_t*>(&lo);
        o.y = *reinterpret_cast<uint32_t*>(&hi);
        ((uint2*)g_x16)[i] = o;
    }
}

// Stage 1: deg[src] += w ; cnt[dst] += 1        (edge_index is int32)
__global__ void deg_kernel(const int* __restrict__ ei,
                           const float* __restrict__ ew) {
    int e = blockIdx.x * blockDim.x + threadIdx.x;
    if (e < N_EDGES) {
        atomicAdd(&g_dinv[ei[e]], ew[e]);
        atomicAdd(&g_cnt[ei[N_EDGES + e]], 1);
    }
}

// ---------------------------------------------------------------------------
// Stage 2: grid-wide 3-phase exclusive scan
// ---------------------------------------------------------------------------
__global__ void blocksum_kernel() {
    int i = blockIdx.x * 256 + threadIdx.x;
    int v = 0;
    if (i < N_NODES) {
        v = g_cnt[i];
        float d = g_dinv[i];
        g_dinv[i] = (d > 0.f) ? rsqrtf(d) : 0.f;
    }
    __shared__ int ws[8];
    int lane = threadIdx.x & 31, wid = threadIdx.x >> 5;
#pragma unroll
    for (int o = 16; o > 0; o >>= 1) v += __shfl_down_sync(0xffffffffu, v, o);
    if (lane == 0) ws[wid] = v;
    __syncthreads();
    if (threadIdx.x == 0) {
        int s = 0;
#pragma unroll
        for (int w = 0; w < 8; w++) s += ws[w];
        g_blocksum[blockIdx.x] = s;
    }
}

__global__ void blockscan_kernel() {
    __shared__ int ws[8];
    int tid = threadIdx.x, lane = tid & 31, wid = tid >> 5;
    int v = (tid < NB) ? g_blocksum[tid] : 0;
    int inc = v;
#pragma unroll
    for (int o = 1; o < 32; o <<= 1) {
        int t = __shfl_up_sync(0xffffffffu, inc, o);
        if (lane >= o) inc += t;
    }
    if (lane == 31) ws[wid] = inc;
    __syncthreads();
    if (wid == 0 && lane < 8) {
        int t = ws[lane];
#pragma unroll
        for (int o = 1; o < 8; o <<= 1) {
            int u = __shfl_up_sync(0xffu, t, o);
            if (lane >= o) t += u;
        }
        ws[lane] = t;
    }
    __syncthreads();
    int excl = inc - v + ((wid > 0) ? ws[wid - 1] : 0);
    if (tid < NB) g_blockoff[tid] = excl;
}

__global__ void rowptr_kernel() {
    int i = blockIdx.x * 256 + threadIdx.x;
    int v = (i < N_NODES) ? g_cnt[i] : 0;
    __shared__ int ws[8];
    int lane = threadIdx.x & 31, wid = threadIdx.x >> 5;
    int inc = v;
#pragma unroll
    for (int o = 1; o < 32; o <<= 1) {
        int t = __shfl_up_sync(0xffffffffu, inc, o);
        if (lane >= o) inc += t;
    }
    if (lane == 31) ws[wid] = inc;
    __syncthreads();
    if (wid == 0 && lane < 8) {
        int t = ws[lane];
#pragma unroll
        for (int o = 1; o < 8; o <<= 1) {
            int u = __shfl_up_sync(0xffu, t, o);
            if (lane >= o) t += u;
        }
        ws[lane] = t;
    }
    __syncthreads();
    int excl = inc - v + ((wid > 0) ? ws[wid - 1] : 0) + g_blockoff[blockIdx.x];
    if (i < N_NODES) { g_rowptr[i] = excl; g_cursor[i] = excl; }
}

// Stage 3: scatter packed (src, norm) into dst-grouped CSR slots
__global__ void scatter_kernel(const int* __restrict__ ei,
                               const float* __restrict__ ew) {
    int e = blockIdx.x * blockDim.x + threadIdx.x;
    if (e < N_EDGES) {
        int s = ei[e];
        int d = ei[N_EDGES + e];
        float nrm = -g_dinv[s] * ew[e] * g_dinv[d];
        int pos = atomicAdd(&g_cursor[d], 1);
        g_edges[pos] = make_int2(s, __float_as_int(nrm));
    }
}

// ---------------------------------------------------------------------------
// Stage 4/5: gather-side propagation (fp16 rows), one warp per dst node.
// ---------------------------------------------------------------------------
__device__ __forceinline__ void fma_h4(float4& acc, float w, uint2 r) {
    __half2 h0 = *reinterpret_cast<__half2*>(&r.x);
    __half2 h1 = *reinterpret_cast<__half2*>(&r.y);
    float2 f0 = __half22float2(h0);
    float2 f1 = __half22float2(h1);
    acc.x += w * f0.x; acc.y += w * f0.y;
    acc.z += w * f1.x; acc.w += w * f1.y;
}

__device__ __forceinline__ void store_h4(__half* dst, float4 acc) {
    __half2 lo = __floats2half2_rn(acc.x, acc.y);
    __half2 hi = __floats2half2_rn(acc.z, acc.w);
    uint2 o;
    o.x = *reinterpret_cast<uint32_t*>(&lo);
    o.y = *reinterpret_cast<uint32_t*>(&hi);
    *reinterpret_cast<uint2*>(dst) = o;
}

__device__ __forceinline__ float4 prop_gather(const __half* __restrict__ in,
                                              int base, int cnt, int lane) {
    float4 acc = make_float4(0.f, 0.f, 0.f, 0.f);
    int j = 0;
    for (; j + 4 <= cnt; j += 4) {
        int2 e0 = g_edges[base + j];
        int2 e1 = g_edges[base + j + 1];
        int2 e2 = g_edges[base + j + 2];
        int2 e3 = g_edges[base + j + 3];
        uint2 r0 = *(const uint2*)(in + (size_t)e0.x * FDIM + lane * 4);
        uint2 r1 = *(const uint2*)(in + (size_t)e1.x * FDIM + lane * 4);
        uint2 r2 = *(const uint2*)(in + (size_t)e2.x * FDIM + lane * 4);
        uint2 r3 = *(const uint2*)(in + (size_t)e3.x * FDIM + lane * 4);
        fma_h4(acc, __int_as_float(e0.y), r0);
        fma_h4(acc, __int_as_float(e1.y), r1);
        fma_h4(acc, __int_as_float(e2.y), r2);
        fma_h4(acc, __int_as_float(e3.y), r3);
    }
    for (; j < cnt; j++) {
        int2 e0 = g_edges[base + j];
        uint2 r0 = *(const uint2*)(in + (size_t)e0.x * FDIM + lane * 4);
        fma_h4(acc, __int_as_float(e0.y), r0);
    }
    return acc;
}

__global__ void prop1_csr_kernel() {
    int node = (blockIdx.x * blockDim.x + threadIdx.x) >> 5;
    int lane = threadIdx.x & 31;
    if (node >= N_NODES) return;
    float4 acc = prop_gather(g_x16, g_rowptr[node], g_cnt[node], lane);
    store_h4(g_T1h + (size_t)node * FDIM + lane * 4, acc);
}

__global__ void prop2_csr_kernel() {
    int node = (blockIdx.x * blockDim.x + threadIdx.x) >> 5;
    int lane = threadIdx.x & 31;
    if (node >= N_NODES) return;
    // P = L_hat @ T1  (finalize folded into the weights)
    float4 acc = prop_gather(g_T1h, g_rowptr[node], g_cnt[node], lane);
    store_h4(g_T2h + (size_t)node * FDIM + lane * 4, acc);
}

// ---------------------------------------------------------------------------
// Stage 6: fused GEMM (2-term tf32: A fp16-exact, B big+delta) + gate + proj
//   BM=64, BN=256 (128 z | 128 h), BK=16, 8 warps = 4M x 2N
//   warp tile: 16 rows x (64 z + 64 h) -> z and h for a cell in SAME thread
// ---------------------------------------------------------------------------
#define BMF       64
#define BKT       16
#define NKB       24
#define A_HSTRIDE 20                       // halves per A smem row (40B, 8-aligned)
#define A_BYTES   (BMF * A_HSTRIDE * 2)    // 2560
#define B_STRIDE  260
#define BT_BYTES  (BKT * B_STRIDE * 4)     // 16640
#define STG_BYTES (A_BYTES + 2 * BT_BYTES) // 35840
#define HN_STRIDE 132
#define SMEM_BYTES (2 * STG_BYTES)         // 71680

extern __shared__ float smem[];

__device__ __forceinline__ void cp_async16(uint32_t saddr, const void* g, int bytes) {
    asm volatile("cp.async.cg.shared.global [%0], [%1], 16, %2;"
                 :: "r"(saddr), "l"(g), "r"(bytes) : "memory");
}
__device__ __forceinline__ void cp_async8(uint32_t saddr, const void* g, int bytes) {
    asm volatile("cp.async.ca.shared.global [%0], [%1], 8, %2;"
                 :: "r"(saddr), "l"(g), "r"(bytes) : "memory");
}

__device__ __forceinline__ void mma_tf32(float* c, const uint32_t* a, const uint32_t* b) {
    asm volatile(
        "mma.sync.aligned.m16n8k8.row.col.f32.tf32.tf32.f32 "
        "{%0,%1,%2,%3}, {%4,%5,%6,%7}, {%8,%9}, {%0,%1,%2,%3};"
        : "+f"(c[0]), "+f"(c[1]), "+f"(c[2]), "+f"(c[3])
        : "r"(a[0]), "r"(a[1]), "r"(a[2]), "r"(a[3]),
          "r"(b[0]), "r"(b[1]));
}

__device__ __forceinline__ float gate_fn(float z, float h) {
    float sig = 1.f / (1.f + __expf(-z));
    return (1.f - sig) * tanhf(h);
}

__global__ __launch_bounds__(256, 2) void fused_kernel(
    const float* __restrict__ bz0, const float* __restrict__ bz1,
    const float* __restrict__ bh0, const float* __restrict__ bh1,
    const float* __restrict__ Wlin, const float* __restrict__ blin,
    float* __restrict__ out)
{
    const int tid  = threadIdx.x;
    const int lane = tid & 31;
    const int wid  = tid >> 5;
    const int wm   = wid & 3;          // 4 M-blocks of 16
    const int wn   = wid >> 2;         // 2 N-groups: 64 z cols + 64 h cols
    const int mwb  = wm * 16;
    const int m0   = blockIdx.x * BMF;

    const uint32_t smem_u32 = (uint32_t)__cvta_generic_to_shared(smem);

    // c[ni<8] = z cols wn*64+ni*8 ; c[ni>=8] = h cols (same columns, +128 in B)
    float c[16][4];
#pragma unroll
    for (int ni = 0; ni < 16; ni++)
#pragma unroll
        for (int q = 0; q < 4; q++) c[ni][q] = 0.f;

    auto load_stage = [&](int kb, int s) {
        const int col = kb * BKT;
        const __half* Asrc;
        int c0;
        if (col < 128)      { Asrc = g_x16; c0 = col; }
        else if (col < 256) { Asrc = g_T1h; c0 = col - 128; }
        else                { Asrc = g_T2h; c0 = col - 256; }

        uint32_t sa  = smem_u32 + (uint32_t)(s * STG_BYTES);
        uint32_t sbb = sa + A_BYTES;
        uint32_t sbd = sbb + BT_BYTES;

        // A tile: 64 rows x 16 halves = 1024 halves -> 4 halves (8B) per thread
        {
            int m  = tid >> 2;
            int c4 = (tid & 3) * 4;
            int node  = m0 + m;
            int bytes = (node < N_NODES) ? 8 : 0;
            int nd    = (node < N_NODES) ? node : 0;
            cp_async8(sa + (uint32_t)(m * (A_HSTRIDE * 2) + c4 * 2),
                      Asrc + (size_t)nd * FDIM + c0 + c4, bytes);
        }
        // B tiles (big + delta): 16 rows x 256 cols = 1024 float4 each
#pragma unroll
        for (int j = 0; j < 4; j++) {
            int idx  = tid + j * 256;
            int jr   = idx >> 6;
            int col4 = (idx & 63) * 4;
            size_t goff = (size_t)(col + jr) * 256 + col4;
            cp_async16(sbb + (uint32_t)(jr * B_STRIDE + col4) * 4u, g_Bb + goff, 16);
            cp_async16(sbd + (uint32_t)(jr * B_STRIDE + col4) * 4u, g_Bd + goff, 16);
        }
        asm volatile("cp.async.commit_group;" ::: "memory");
    };

    load_stage(0, 0);

    const int ar = lane >> 2;
    const int ac = lane & 3;

    for (int kb = 0; kb < NKB; kb++) {
        int s = kb & 1;
        if (kb + 1 < NKB) {
            load_stage(kb + 1, s ^ 1);
            asm volatile("cp.async.wait_group 1;" ::: "memory");
        } else {
            asm volatile("cp.async.wait_group 0;" ::: "memory");
        }
        __syncthreads();

        const char*     sbase = (const char*)smem + s * STG_BYTES;
        const __half*   A  = (const __half*)sbase;
        const uint32_t* Bb = (const uint32_t*)(sbase + A_BYTES);
        const uint32_t* Bd = (const uint32_t*)(sbase + A_BYTES + BT_BYTES);

#pragma unroll
        for (int k8 = 0; k8 < 2; k8++) {
            const int kk = k8 * 8;
            const int r0 = mwb + ar;

            // A fragment: fp16 is EXACT in tf32 -> no delta term for A
            uint32_t ab[4];
            ab[0] = f2tf32(__half2float(A[r0 * A_HSTRIDE + kk + ac]));
            ab[1] = f2tf32(__half2float(A[(r0 + 8) * A_HSTRIDE + kk + ac]));
            ab[2] = f2tf32(__half2float(A[r0 * A_HSTRIDE + kk + ac + 4]));
            ab[3] = f2tf32(__half2float(A[(r0 + 8) * A_HSTRIDE + kk + ac + 4]));

#pragma unroll
            for (int half = 0; half < 2; half++) {    // 0 = z cols, 1 = h cols
                uint32_t bb[8][2], bd[8][2];
#pragma unroll
                for (int ni = 0; ni < 8; ni++) {
                    int bc = half * 128 + wn * 64 + ni * 8 + ar;
                    int br = kk + ac;
                    bb[ni][0] = Bb[br * B_STRIDE + bc];
                    bb[ni][1] = Bb[(br + 4) * B_STRIDE + bc];
                    bd[ni][0] = Bd[br * B_STRIDE + bc];
                    bd[ni][1] = Bd[(br + 4) * B_STRIDE + bc];
                }
#pragma unroll
                for (int ni = 0; ni < 8; ni++) {
                    mma_tf32(c[half * 8 + ni], ab, bb[ni]);
                    mma_tf32(c[half * 8 + ni], ab, bd[ni]);
                }
            }
        }
        __syncthreads();
    }

    // ---- epilogue: gate in registers (z and h live in the SAME thread) ----
    float* Hn    = smem;                        // [64][132]
    float* WlinT = smem + BMF * HN_STRIDE;      // [10][128]
    for (int idx = tid; idx < TDIM * HDIM; idx += 256) {
        int t = idx % TDIM;
        int h = idx / TDIM;
        WlinT[t * HDIM + h] = Wlin[h * TDIM + t];
    }

    const int mb = mwb + ar;
#pragma unroll
    for (int ni = 0; ni < 8; ni++) {
        int n = wn * 64 + ni * 8 + ac * 2;
        float bz_a = bz0[n] + bz1[n];
        float bz_b = bz0[n + 1] + bz1[n + 1];
        float bh_a = bh0[n] + bh1[n];
        float bh_b = bh0[n + 1] + bh1[n + 1];
        Hn[mb * HN_STRIDE + n]           = gate_fn(c[ni][0] + bz_a, c[8 + ni][0] + bh_a);
        Hn[mb * HN_STRIDE + n + 1]       = gate_fn(c[ni][1] + bz_b, c[8 + ni][1] + bh_b);
        Hn[(mb + 8) * HN_STRIDE + n]     = gate_fn(c[ni][2] + bz_a, c[8 + ni][2] + bh_a);
        Hn[(mb + 8) * HN_STRIDE + n + 1] = gate_fn(c[ni][3] + bz_b, c[8 + ni][3] + bh_b);
    }
    __syncthreads();

    // ---- output projection: thread = (row m, half g); 5 t's per thread ----
    if (tid < 2 * BMF) {
        int m = tid >> 1;
        int g = tid & 1;
        int node = m0 + m;
        if (node < N_NODES) {
            float acc[5];
#pragma unroll
            for (int j = 0; j < 5; j++) acc[j] = blin[g * 5 + j];
            const float* hrow = Hn + m * HN_STRIDE;
#pragma unroll 8
            for (int h = 0; h < HDIM; h++) {
                float v = hrow[h];
#pragma unroll
                for (int j = 0; j < 5; j++)
                    acc[j] += v * WlinT[(g * 5 + j) * HDIM + h];
            }
#pragma unroll
            for (int j = 0; j < 5; j++)
                out[(size_t)node * TDIM + g * 5 + j] = acc[j];
        }
    }
}

// ---------------------------------------------------------------------------
// Launch
// ---------------------------------------------------------------------------
extern "C" void kernel_launch(void* const* d_in, const int* in_sizes, int n_in,
                              void* d_out, int out_size) {
    const float* x    = (const float*)d_in[0];
    const int*   ei   = (const int*)d_in[1];      // int32 (JAX x64 disabled)
    const float* ew   = (const float*)d_in[2];
    const float* Wxz  = (const float*)d_in[3];
    const float* bxz  = (const float*)d_in[4];
    const float* bhz  = (const float*)d_in[6];
    const float* Wxh  = (const float*)d_in[11];
    const float* bxh  = (const float*)d_in[12];
    const float* bhh  = (const float*)d_in[14];
    const float* Wlin = (const float*)d_in[15];
    const float* blin = (const float*)d_in[16];
    float*       out  = (float*)d_out;

    cudaFuncSetAttribute(fused_kernel,
                         cudaFuncAttributeMaxDynamicSharedMemorySize, SMEM_BYTES);

    // Preamble
    split_kernel<<<384, 256>>>(Wxz, Wxh);                        // fold+split+init
    cvtx_kernel<<<(N_NODES * FDIM / 4 + 255) / 256, 256>>>(x);   // x -> fp16
    deg_kernel<<<(N_EDGES + 255) / 256, 256>>>(ei, ew);
    blocksum_kernel<<<NB, 256>>>();
    blockscan_kernel<<<1, 256>>>();
    rowptr_kernel<<<NB, 256>>>();
    scatter_kernel<<<(N_EDGES + 255) / 256, 256>>>(ei, ew);

    // Gather-side propagation (fp16 rows)
    const int PROP_BLOCKS = (N_NODES * 32 + 255) / 256;
    prop1_csr_kernel<<<PROP_BLOCKS, 256>>>();
    prop2_csr_kernel<<<PROP_BLOCKS, 256>>>();

    fused_kernel<<<(N_NODES + BMF - 1) / BMF, 256, SMEM_BYTES>>>(
        bxz, bhz, bxh, bhh, Wlin, blin, out);
}

// round 14
// speedup vs baseline: 2.9894x; 1.7615x over previous
#include <cuda_runtime.h>
#include <cuda_fp16.h>
#include <cstdint>

#define N_NODES 50000
#define N_EDGES 800000
#define FDIM    128
#define HDIM    128
#define TDIM    10
#define NB      ((N_NODES + 255) / 256)    // 196 scan blocks

// Scratch (device globals) — only ever referenced from DEVICE code.
__device__ __align__(16) float g_dinv[N_NODES];
__device__ int  g_cnt[N_NODES];
__device__ int  g_rowptr[N_NODES];
__device__ int  g_cursor[N_NODES];
__device__ int  g_blocksum[NB];
__device__ int  g_blockoff[NB];
__device__ __align__(16) int2   g_edges[N_EDGES];
// fp16 A-side data path
__device__ __align__(16) __half g_x16[N_NODES * FDIM];
__device__ __align__(16) __half g_T1h[N_NODES * FDIM];
__device__ __align__(16) __half g_T2h[N_NODES * FDIM];   // P = L_hat @ T1
// fp16 B, TRANSPOSED [n=256][k=384], weight-folded:
//   k<128: W0-W2 ; 128<=k<256: W1 ; k>=256: 2*W2   (n<128: z | n>=128: h)
__device__ __align__(16) __half g_Bt[256 * 384];

// ---------------------------------------------------------------------------
// Stage 0a: weight fold -> fp16 transposed B + init (one launch)
// ---------------------------------------------------------------------------
__global__ void split_kernel(const float* __restrict__ Wz,
                             const float* __restrict__ Wh) {
    int idx = blockIdx.x * blockDim.x + threadIdx.x;
    if (idx < N_NODES) { g_dinv[idx] = 0.f; g_cnt[idx] = 0; }
    if (idx < 256 * 384) {
        int n = idx / 384;
        int k = idx % 384;
        const float* W = (n < 128) ? Wz : Wh;
        int cc = n & 127;
        float v;
        if (k < 128)      v = W[k * 128 + cc] - W[(k + 256) * 128 + cc];  // W0 - W2
        else if (k < 256) v = W[k * 128 + cc];                            // W1
        else              v = 2.f * W[k * 128 + cc];                      // 2*W2
        g_Bt[idx] = __float2half_rn(v);
    }
}

// Stage 0b: x -> fp16 copy
__global__ void cvtx_kernel(const float* __restrict__ x) {
    int i = blockIdx.x * blockDim.x + threadIdx.x;
    if (i < N_NODES * FDIM / 4) {
        float4 v = ((const float4*)x)[i];
        __half2 lo = __floats2half2_rn(v.x, v.y);
        __half2 hi = __floats2half2_rn(v.z, v.w);
        uint2 o;
        o.x = *reinterpret_cast<uint32_t*>(&lo);
        o.y = *reinterpret_cast<uint32_t*>(&hi);
        ((uint2*)g_x16)[i] = o;
    }
}

// Stage 1: deg[src] += w ; cnt[dst] += 1        (edge_index is int32)
__global__ void deg_kernel(const int* __restrict__ ei,
                           const float* __restrict__ ew) {
    int e = blockIdx.x * blockDim.x + threadIdx.x;
    if (e < N_EDGES) {
        atomicAdd(&g_dinv[ei[e]], ew[e]);
        atomicAdd(&g_cnt[ei[N_EDGES + e]], 1);
    }
}

// ---------------------------------------------------------------------------
// Stage 2: grid-wide 3-phase exclusive scan
// ---------------------------------------------------------------------------
__global__ void blocksum_kernel() {
    int i = blockIdx.x * 256 + threadIdx.x;
    int v = 0;
    if (i < N_NODES) {
        v = g_cnt[i];
        float d = g_dinv[i];
        g_dinv[i] = (d > 0.f) ? rsqrtf(d) : 0.f;
    }
    __shared__ int ws[8];
    int lane = threadIdx.x & 31, wid = threadIdx.x >> 5;
#pragma unroll
    for (int o = 16; o > 0; o >>= 1) v += __shfl_down_sync(0xffffffffu, v, o);
    if (lane == 0) ws[wid] = v;
    __syncthreads();
    if (threadIdx.x == 0) {
        int s = 0;
#pragma unroll
        for (int w = 0; w < 8; w++) s += ws[w];
        g_blocksum[blockIdx.x] = s;
    }
}

__global__ void blockscan_kernel() {
    __shared__ int ws[8];
    int tid = threadIdx.x, lane = tid & 31, wid = tid >> 5;
    int v = (tid < NB) ? g_blocksum[tid] : 0;
    int inc = v;
#pragma unroll
    for (int o = 1; o < 32; o <<= 1) {
        int t = __shfl_up_sync(0xffffffffu, inc, o);
        if (lane >= o) inc += t;
    }
    if (lane == 31) ws[wid] = inc;
    __syncthreads();
    if (wid == 0 && lane < 8) {
        int t = ws[lane];
#pragma unroll
        for (int o = 1; o < 8; o <<= 1) {
            int u = __shfl_up_sync(0xffu, t, o);
            if (lane >= o) t += u;
        }
        ws[lane] = t;
    }
    __syncthreads();
    int excl = inc - v + ((wid > 0) ? ws[wid - 1] : 0);
    if (tid < NB) g_blockoff[tid] = excl;
}

__global__ void rowptr_kernel() {
    int i = blockIdx.x * 256 + threadIdx.x;
    int v = (i < N_NODES) ? g_cnt[i] : 0;
    __shared__ int ws[8];
    int lane = threadIdx.x & 31, wid = threadIdx.x >> 5;
    int inc = v;
#pragma unroll
    for (int o = 1; o < 32; o <<= 1) {
        int t = __shfl_up_sync(0xffffffffu, inc, o);
        if (lane >= o) inc += t;
    }
    if (lane == 31) ws[wid] = inc;
    __syncthreads();
    if (wid == 0 && lane < 8) {
        int t = ws[lane];
#pragma unroll
        for (int o = 1; o < 8; o <<= 1) {
            int u = __shfl_up_sync(0xffu, t, o);
            if (lane >= o) t += u;
        }
        ws[lane] = t;
    }
    __syncthreads();
    int excl = inc - v + ((wid > 0) ? ws[wid - 1] : 0) + g_blockoff[blockIdx.x];
    if (i < N_NODES) { g_rowptr[i] = excl; g_cursor[i] = excl; }
}

// Stage 3: scatter packed (src, norm) into dst-grouped CSR slots
__global__ void scatter_kernel(const int* __restrict__ ei,
                               const float* __restrict__ ew) {
    int e = blockIdx.x * blockDim.x + threadIdx.x;
    if (e < N_EDGES) {
        int s = ei[e];
        int d = ei[N_EDGES + e];
        float nrm = -g_dinv[s] * ew[e] * g_dinv[d];
        int pos = atomicAdd(&g_cursor[d], 1);
        g_edges[pos] = make_int2(s, __float_as_int(nrm));
    }
}

// ---------------------------------------------------------------------------
// Stage 4/5: gather-side propagation (fp16 rows), one warp per dst node.
// ---------------------------------------------------------------------------
__device__ __forceinline__ void fma_h4(float4& acc, float w, uint2 r) {
    __half2 h0 = *reinterpret_cast<__half2*>(&r.x);
    __half2 h1 = *reinterpret_cast<__half2*>(&r.y);
    float2 f0 = __half22float2(h0);
    float2 f1 = __half22float2(h1);
    acc.x += w * f0.x; acc.y += w * f0.y;
    acc.z += w * f1.x; acc.w += w * f1.y;
}

__device__ __forceinline__ void store_h4(__half* dst, float4 acc) {
    __half2 lo = __floats2half2_rn(acc.x, acc.y);
    __half2 hi = __floats2half2_rn(acc.z, acc.w);
    uint2 o;
    o.x = *reinterpret_cast<uint32_t*>(&lo);
    o.y = *reinterpret_cast<uint32_t*>(&hi);
    *reinterpret_cast<uint2*>(dst) = o;
}

__device__ __forceinline__ float4 prop_gather(const __half* __restrict__ in,
                                              int base, int cnt, int lane) {
    float4 acc = make_float4(0.f, 0.f, 0.f, 0.f);
    int j = 0;
    for (; j + 4 <= cnt; j += 4) {
        int2 e0 = g_edges[base + j];
        int2 e1 = g_edges[base + j + 1];
        int2 e2 = g_edges[base + j + 2];
        int2 e3 = g_edges[base + j + 3];
        uint2 r0 = *(const uint2*)(in + (size_t)e0.x * FDIM + lane * 4);
        uint2 r1 = *(const uint2*)(in + (size_t)e1.x * FDIM + lane * 4);
        uint2 r2 = *(const uint2*)(in + (size_t)e2.x * FDIM + lane * 4);
        uint2 r3 = *(const uint2*)(in + (size_t)e3.x * FDIM + lane * 4);
        fma_h4(acc, __int_as_float(e0.y), r0);
        fma_h4(acc, __int_as_float(e1.y), r1);
        fma_h4(acc, __int_as_float(e2.y), r2);
        fma_h4(acc, __int_as_float(e3.y), r3);
    }
    for (; j < cnt; j++) {
        int2 e0 = g_edges[base + j];
        uint2 r0 = *(const uint2*)(in + (size_t)e0.x * FDIM + lane * 4);
        fma_h4(acc, __int_as_float(e0.y), r0);
    }
    return acc;
}

__global__ void prop1_csr_kernel() {
    int node = (blockIdx.x * blockDim.x + threadIdx.x) >> 5;
    int lane = threadIdx.x & 31;
    if (node >= N_NODES) return;
    float4 acc = prop_gather(g_x16, g_rowptr[node], g_cnt[node], lane);
    store_h4(g_T1h + (size_t)node * FDIM + lane * 4, acc);
}

__global__ void prop2_csr_kernel() {
    int node = (blockIdx.x * blockDim.x + threadIdx.x) >> 5;
    int lane = threadIdx.x & 31;
    if (node >= N_NODES) return;
    float4 acc = prop_gather(g_T1h, g_rowptr[node], g_cnt[node], lane);
    store_h4(g_T2h + (size_t)node * FDIM + lane * 4, acc);
}

// ---------------------------------------------------------------------------
// Stage 6: fused GEMM (pure fp16 MMA m16n8k16, fp32 accum) + gate + proj
//   BM=64, BN=256 (128 z | 128 h), BK=16, 8 warps = 4M x 2N
//   warp tile: 16 rows x (64 z + 64 h cols); z,h cell pairs in SAME thread
// ---------------------------------------------------------------------------
#define BMF       64
#define BKT       16
#define NKB       24
#define A_HSTRIDE 20                        // halves per A smem row (40 B)
#define A_BYTES   (BMF * A_HSTRIDE * 2)     // 2560
#define B_HSTRIDE 24                        // halves per B smem row (48 B, bank-clean)
#define B_BYTES   (256 * B_HSTRIDE * 2)     // 12288
#define STG_BYTES (A_BYTES + B_BYTES)       // 14848
#define HN_STRIDE 132
#define EPI_BYTES ((BMF * HN_STRIDE + TDIM * HDIM) * 4)   // 33792 + 5120 = 38912
#define SMEM_BYTES ((2 * STG_BYTES) > EPI_BYTES ? (2 * STG_BYTES) : EPI_BYTES) // 38912

extern __shared__ float smem[];

__device__ __forceinline__ void cp_async16(uint32_t saddr, const void* g, int bytes) {
    asm volatile("cp.async.cg.shared.global [%0], [%1], 16, %2;"
                 :: "r"(saddr), "l"(g), "r"(bytes) : "memory");
}
__device__ __forceinline__ void cp_async8(uint32_t saddr, const void* g, int bytes) {
    asm volatile("cp.async.ca.shared.global [%0], [%1], 8, %2;"
                 :: "r"(saddr), "l"(g), "r"(bytes) : "memory");
}

__device__ __forceinline__ void mma_f16(float* c, const uint32_t* a, const uint32_t* b) {
    asm volatile(
        "mma.sync.aligned.m16n8k16.row.col.f32.f16.f16.f32 "
        "{%0,%1,%2,%3}, {%4,%5,%6,%7}, {%8,%9}, {%0,%1,%2,%3};"
        : "+f"(c[0]), "+f"(c[1]), "+f"(c[2]), "+f"(c[3])
        : "r"(a[0]), "r"(a[1]), "r"(a[2]), "r"(a[3]),
          "r"(b[0]), "r"(b[1]));
}

__device__ __forceinline__ float gate_fn(float z, float h) {
    float sig = 1.f / (1.f + __expf(-z));
    return (1.f - sig) * tanhf(h);
}

__global__ __launch_bounds__(256, 2) void fused_kernel(
    const float* __restrict__ bz0, const float* __restrict__ bz1,
    const float* __restrict__ bh0, const float* __restrict__ bh1,
    const float* __restrict__ Wlin, const float* __restrict__ blin,
    float* __restrict__ out)
{
    const int tid  = threadIdx.x;
    const int lane = tid & 31;
    const int wid  = tid >> 5;
    const int wm   = wid & 3;          // 4 M-blocks of 16
    const int wn   = wid >> 2;         // 2 N-groups of 64
    const int mwb  = wm * 16;
    const int m0   = blockIdx.x * BMF;

    const uint32_t smem_u32 = (uint32_t)__cvta_generic_to_shared(smem);

    // c[ni<8] = z cols (wn*64 + ni*8), c[ni>=8] = h cols (same cols, n+128)
    float c[16][4];
#pragma unroll
    for (int ni = 0; ni < 16; ni++)
#pragma unroll
        for (int q = 0; q < 4; q++) c[ni][q] = 0.f;

    auto load_stage = [&](int kb, int s) {
        const int col = kb * BKT;
        const __half* Asrc;
        int c0;
        if (col < 128)      { Asrc = g_x16; c0 = col; }
        else if (col < 256) { Asrc = g_T1h; c0 = col - 128; }
        else                { Asrc = g_T2h; c0 = col - 256; }

        uint32_t sa = smem_u32 + (uint32_t)(s * STG_BYTES);
        uint32_t sb = sa + A_BYTES;

        // A tile: 64 rows x 16 halves -> 8 B per thread
        {
            int m  = tid >> 2;
            int c4 = (tid & 3) * 4;
            int node  = m0 + m;
            int bytes = (node < N_NODES) ? 8 : 0;
            int nd    = (node < N_NODES) ? node : 0;
            cp_async8(sa + (uint32_t)(m * (A_HSTRIDE * 2) + c4 * 2),
                      Asrc + (size_t)nd * FDIM + c0 + c4, bytes);
        }
        // B tile: 256 n-rows x 16 k halves (32 B contiguous in g_Bt) per row
        {
            const __half* src = g_Bt + (size_t)tid * 384 + col;
            uint32_t d = sb + (uint32_t)(tid * (B_HSTRIDE * 2));
            cp_async16(d, src, 16);
            cp_async16(d + 16, src + 8, 16);
        }
        asm volatile("cp.async.commit_group;" ::: "memory");
    };

    load_stage(0, 0);

    const int ar = lane >> 2;     // 0..7
    const int ac = lane & 3;      // 0..3

    for (int kb = 0; kb < NKB; kb++) {
        int s = kb & 1;
        if (kb + 1 < NKB) {
            load_stage(kb + 1, s ^ 1);
            asm volatile("cp.async.wait_group 1;" ::: "memory");
        } else {
            asm volatile("cp.async.wait_group 0;" ::: "memory");
        }
        __syncthreads();

        const char*   sbase = (const char*)smem + s * STG_BYTES;
        const __half* A  = (const __half*)sbase;
        const __half* Bt = (const __half*)(sbase + A_BYTES);

        // A fragment (m16 x k16, row-major)
        const int r0 = mwb + ar;
        uint32_t a[4];
        a[0] = *(const uint32_t*)(A + r0 * A_HSTRIDE + 2 * ac);
        a[1] = *(const uint32_t*)(A + (r0 + 8) * A_HSTRIDE + 2 * ac);
        a[2] = *(const uint32_t*)(A + r0 * A_HSTRIDE + 2 * ac + 8);
        a[3] = *(const uint32_t*)(A + (r0 + 8) * A_HSTRIDE + 2 * ac + 8);

#pragma unroll
        for (int half = 0; half < 2; half++) {     // 0 = z, 1 = h
#pragma unroll
            for (int ni = 0; ni < 8; ni++) {
                int n = half * 128 + wn * 64 + ni * 8 + ar;
                uint32_t b[2];
                b[0] = *(const uint32_t*)(Bt + n * B_HSTRIDE + 2 * ac);
                b[1] = *(const uint32_t*)(Bt + n * B_HSTRIDE + 2 * ac + 8);
                mma_f16(c[half * 8 + ni], a, b);
            }
        }
        __syncthreads();
    }

    // ---- epilogue: gate in registers (z and h in the SAME thread) ----
    float* Hn    = smem;                        // [64][132]
    float* WlinT = smem + BMF * HN_STRIDE;      // [10][128]
    for (int idx = tid; idx < TDIM * HDIM; idx += 256) {
        int t = idx % TDIM;
        int h = idx / TDIM;
        WlinT[t * HDIM + h] = Wlin[h * TDIM + t];
    }

    const int mb = mwb + ar;
#pragma unroll
    for (int ni = 0; ni < 8; ni++) {
        int n = wn * 64 + ni * 8 + ac * 2;
        float bz_a = bz0[n] + bz1[n];
        float bz_b = bz0[n + 1] + bz1[n + 1];
        float bh_a = bh0[n] + bh1[n];
        float bh_b = bh0[n + 1] + bh1[n + 1];
        Hn[mb * HN_STRIDE + n]           = gate_fn(c[ni][0] + bz_a, c[8 + ni][0] + bh_a);
        Hn[mb * HN_STRIDE + n + 1]       = gate_fn(c[ni][1] + bz_b, c[8 + ni][1] + bh_b);
        Hn[(mb + 8) * HN_STRIDE + n]     = gate_fn(c[ni][2] + bz_a, c[8 + ni][2] + bh_a);
        Hn[(mb + 8) * HN_STRIDE + n + 1] = gate_fn(c[ni][3] + bz_b, c[8 + ni][3] + bh_b);
    }
    __syncthreads();

    // ---- output projection: thread = (row m, half g); 5 t's per thread ----
    if (tid < 2 * BMF) {
        int m = tid >> 1;
        int g = tid & 1;
        int node = m0 + m;
        if (node < N_NODES) {
            float acc[5];
#pragma unroll
            for (int j = 0; j < 5; j++) acc[j] = blin[g * 5 + j];
            const float* hrow = Hn + m * HN_STRIDE;
#pragma unroll 8
            for (int h = 0; h < HDIM; h++) {
                float v = hrow[h];
#pragma unroll
                for (int j = 0; j < 5; j++)
                    acc[j] += v * WlinT[(g * 5 + j) * HDIM + h];
            }
#pragma unroll
            for (int j = 0; j < 5; j++)
                out[(size_t)node * TDIM + g * 5 + j] = acc[j];
        }
    }
}

// ---------------------------------------------------------------------------
// Launch
// ---------------------------------------------------------------------------
extern "C" void kernel_launch(void* const* d_in, const int* in_sizes, int n_in,
                              void* d_out, int out_size) {
    const float* x    = (const float*)d_in[0];
    const int*   ei   = (const int*)d_in[1];      // int32 (JAX x64 disabled)
    const float* ew   = (const float*)d_in[2];
    const float* Wxz  = (const float*)d_in[3];
    const float* bxz  = (const float*)d_in[4];
    const float* bhz  = (const float*)d_in[6];
    const float* Wxh  = (const float*)d_in[11];
    const float* bxh  = (const float*)d_in[12];
    const float* bhh  = (const float*)d_in[14];
    const float* Wlin = (const float*)d_in[15];
    const float* blin = (const float*)d_in[16];
    float*       out  = (float*)d_out;

    cudaFuncSetAttribute(fused_kernel,
                         cudaFuncAttributeMaxDynamicSharedMemorySize, SMEM_BYTES);

    // Preamble
    split_kernel<<<384, 256>>>(Wxz, Wxh);                        // fold -> fp16 B^T + init
    cvtx_kernel<<<(N_NODES * FDIM / 4 + 255) / 256, 256>>>(x);   // x -> fp16
    deg_kernel<<<(N_EDGES + 255) / 256, 256>>>(ei, ew);
    blocksum_kernel<<<NB, 256>>>();
    blockscan_kernel<<<1, 256>>>();
    rowptr_kernel<<<NB, 256>>>();
    scatter_kernel<<<(N_EDGES + 255) / 256, 256>>>(ei, ew);

    // Gather-side propagation (fp16 rows)
    const int PROP_BLOCKS = (N_NODES * 32 + 255) / 256;
    prop1_csr_kernel<<<PROP_BLOCKS, 256>>>();
    prop2_csr_kernel<<<PROP_BLOCKS, 256>>>();

    fused_kernel<<<(N_NODES + BMF - 1) / BMF, 256, SMEM_BYTES>>>(
        bxz, bhz, bxh, bhh, Wlin, blin, out);
}